// round 13
// baseline (speedup 1.0000x reference)
#include <cuda_runtime.h>
#include <cstdint>
#include <math.h>

// ---------------- problem constants ----------------
#define SEQ     2048
#define DMODEL  2048
#define KVDIM   512
#define NHEADS  16
#define DK      128
#define NQKV    (DMODEL + 2 * KVDIM)    // 3072

// ---------------- scratch ----------------
__device__ float g_QKV[SEQ * NQKV];
__device__ float g_Y  [SEQ * DMODEL];

// =====================================================================
// helpers
// =====================================================================
__device__ __forceinline__ float rnaf(float x) {
    uint32_t u;
    asm("cvt.rna.tf32.f32 %0, %1;" : "=r"(u) : "f"(x));
    return __uint_as_float(u);
}
__device__ __forceinline__ uint32_t rnau(uint32_t x) {
    uint32_t u;
    asm("cvt.rna.tf32.f32 %0, %1;" : "=r"(u) : "f"(__uint_as_float(x)));
    return u;
}

__device__ __forceinline__ void cpasync16(uint32_t saddr, const void* gaddr) {
    asm volatile("cp.async.cg.shared.global [%0], [%1], 16;" :: "r"(saddr), "l"(gaddr) : "memory");
}

__device__ __forceinline__ void mma_tf32(float c[4], const uint32_t a[4], const uint32_t b[2]) {
    asm volatile(
        "mma.sync.aligned.m16n8k8.row.col.f32.tf32.tf32.f32 "
        "{%0,%1,%2,%3}, {%4,%5,%6,%7}, {%8,%9}, {%0,%1,%2,%3};"
        : "+f"(c[0]), "+f"(c[1]), "+f"(c[2]), "+f"(c[3])
        : "r"(a[0]), "r"(a[1]), "r"(a[2]), "r"(a[3]), "r"(b[0]), "r"(b[1]));
}

__device__ __forceinline__ void ldsm_x4(uint32_t r[4], uint32_t addr) {
    asm volatile("ldmatrix.sync.aligned.m8n8.x4.shared.b16 {%0,%1,%2,%3}, [%4];"
                 : "=r"(r[0]), "=r"(r[1]), "=r"(r[2]), "=r"(r[3]) : "r"(addr));
}

// =====================================================================
// GEMM common config: CTA 128x128, 8 warps (2x4), warp tile 64x32,
// BK=32, 3-stage cp.async, 2 CTAs/SM.
// =====================================================================
#define BK      32
#define PAD     36
#define TILE_F  (128 * PAD)
#define STAGE_F (2 * TILE_F)
#define NSTAGE  3
#define GEMM_SMEM_BYTES (NSTAGE * STAGE_F * 4)

// ---------------------------------------------------------------------
// QKV projection GEMM: A = x (raw fp32), B selected from Wq/Wk/Wv per
// CTA column. Fragments rna-rounded in registers (A and B); output
// rna-rounded with bias. C layout: [SEQ, NQKV].
// ---------------------------------------------------------------------
__global__ __launch_bounds__(256, 2) void gemm_qkv(
    const float* __restrict__ x,
    const float* __restrict__ Wq, const float* __restrict__ Wk,
    const float* __restrict__ Wv,
    const float* __restrict__ bq, const float* __restrict__ bk,
    const float* __restrict__ bv,
    float* __restrict__ C)
{
    extern __shared__ float sm[];
    const int K = DMODEL, N = NQKV;

    const int tid  = threadIdx.x;
    const int wid  = tid >> 5;
    const int lane = tid & 31;
    const int gid  = lane >> 2;
    const int tig  = lane & 3;
    const int wm   = wid >> 2;
    const int wn   = wid & 3;
    const int bm   = blockIdx.y * 128;
    const int bn   = blockIdx.x * 128;
    const int nchunk = K >> 5;

    // per-CTA weight/bias select (128-col tiles align with 2048/512/512)
    const float* Bsel;
    const float* bsel;
    int bnl;
    if (bn < DMODEL)              { Bsel = Wq; bsel = bq; bnl = bn; }
    else if (bn < DMODEL + KVDIM) { Bsel = Wk; bsel = bk; bnl = bn - DMODEL; }
    else                          { Bsel = Wv; bsel = bv; bnl = bn - DMODEL - KVDIM; }

    const int arow = lane & 15;
    const int acsh = (lane >> 4) * 4;
    const int brow = ((lane >> 4) << 3) + (lane & 7);
    const int bcsh = ((lane >> 3) & 1) * 4;

    const uint32_t smem_u32 = (uint32_t)__cvta_generic_to_shared(sm);

    auto load_chunk = [&](int s, int j) {
        const uint32_t sA = smem_u32 + (s * STAGE_F) * 4;
        const uint32_t sB = sA + TILE_F * 4;
        const float* Ag = x + (size_t)bm * K + j * BK;
        const float* Bg = Bsel + (size_t)bnl * K + j * BK;
#pragma unroll
        for (int it = 0; it < 4; it++) {
            const int idx = tid + it * 256;
            const int r = idx >> 3;
            const int c = idx & 7;
            const uint32_t soff = (r * PAD + c * 4) * 4;
            cpasync16(sA + soff, Ag + (size_t)r * K + c * 4);
            cpasync16(sB + soff, Bg + (size_t)r * K + c * 4);
        }
        asm volatile("cp.async.commit_group;" ::: "memory");
    };

    float acc[4][4][4];
#pragma unroll
    for (int mf = 0; mf < 4; mf++)
#pragma unroll
        for (int nf = 0; nf < 4; nf++)
#pragma unroll
            for (int q = 0; q < 4; q++) acc[mf][nf][q] = 0.0f;

    load_chunk(0, 0);
    load_chunk(1, 1);

    int cs = 0;
    int ls = 2;
    for (int i = 0; i < nchunk; i++) {
        if (i + 1 < nchunk) {
            asm volatile("cp.async.wait_group 1;" ::: "memory");
        } else {
            asm volatile("cp.async.wait_group 0;" ::: "memory");
        }
        __syncthreads();

        const int j = i + 2;
        if (j < nchunk) {
            load_chunk(ls, j);
            ls = (ls == NSTAGE - 1) ? 0 : ls + 1;
        }

        const uint32_t stA = smem_u32 + (cs * STAGE_F) * 4;
        const uint32_t stB = stA + TILE_F * 4;
        const uint32_t aAddr = stA + ((wm * 64 + arow) * PAD + acsh) * 4;
        const uint32_t bAddr = stB + ((wn * 32 + brow) * PAD + bcsh) * 4;
        cs = (cs == NSTAGE - 1) ? 0 : cs + 1;

#pragma unroll
        for (int kk = 0; kk < 4; kk++) {
            const int k0 = kk * 8;
            uint32_t af[4][4];
#pragma unroll
            for (int mf = 0; mf < 4; mf++) {
                ldsm_x4(af[mf], aAddr + (mf * 16 * PAD + k0) * 4);
#pragma unroll
                for (int q = 0; q < 4; q++) af[mf][q] = rnau(af[mf][q]);
            }
            uint32_t bf[4][2];
#pragma unroll
            for (int np = 0; np < 2; np++) {
                uint32_t bt[4];
                ldsm_x4(bt, bAddr + (np * 16 * PAD + k0) * 4);
#pragma unroll
                for (int q = 0; q < 4; q++) bt[q] = rnau(bt[q]);
                bf[2 * np][0]     = bt[0]; bf[2 * np][1]     = bt[1];
                bf[2 * np + 1][0] = bt[2]; bf[2 * np + 1][1] = bt[3];
            }
#pragma unroll
            for (int mf = 0; mf < 4; mf++)
#pragma unroll
                for (int nf = 0; nf < 4; nf++)
                    mma_tf32(acc[mf][nf], af[mf], bf[nf]);
        }
    }

#pragma unroll
    for (int mf = 0; mf < 4; mf++) {
        const int row = bm + wm * 64 + mf * 16 + gid;
#pragma unroll
        for (int nf = 0; nf < 4; nf++) {
            const int cl = wn * 32 + nf * 8 + 2 * tig;
            const float b0 = bsel[bnl + cl], b1 = bsel[bnl + cl + 1];
            float2 v0, v1;
            v0.x = rnaf(acc[mf][nf][0] + b0); v0.y = rnaf(acc[mf][nf][1] + b1);
            v1.x = rnaf(acc[mf][nf][2] + b0); v1.y = rnaf(acc[mf][nf][3] + b1);
            *(float2*)&C[(size_t)row * N + bn + cl]       = v0;
            *(float2*)&C[(size_t)(row + 8) * N + bn + cl] = v1;
        }
    }
}

// ---------------------------------------------------------------------
// Output projection GEMM: A = Y (pre-rounded tf32), B = Wo (raw; B
// fragments rna-rounded in registers). Exact fp32 output + bias.
// ---------------------------------------------------------------------
__global__ __launch_bounds__(256, 2) void gemm_out(
    const float* __restrict__ A, const float* __restrict__ B,
    const float* __restrict__ bias, float* __restrict__ C)
{
    extern __shared__ float sm[];
    const int K = DMODEL, N = DMODEL;

    const int tid  = threadIdx.x;
    const int wid  = tid >> 5;
    const int lane = tid & 31;
    const int gid  = lane >> 2;
    const int tig  = lane & 3;
    const int wm   = wid >> 2;
    const int wn   = wid & 3;
    const int bm   = blockIdx.y * 128;
    const int bn   = blockIdx.x * 128;
    const int nchunk = K >> 5;

    const int arow = lane & 15;
    const int acsh = (lane >> 4) * 4;
    const int brow = ((lane >> 4) << 3) + (lane & 7);
    const int bcsh = ((lane >> 3) & 1) * 4;

    const uint32_t smem_u32 = (uint32_t)__cvta_generic_to_shared(sm);

    auto load_chunk = [&](int s, int j) {
        const uint32_t sA = smem_u32 + (s * STAGE_F) * 4;
        const uint32_t sB = sA + TILE_F * 4;
        const float* Ag = A + (size_t)bm * K + j * BK;
        const float* Bg = B + (size_t)bn * K + j * BK;
#pragma unroll
        for (int it = 0; it < 4; it++) {
            const int idx = tid + it * 256;
            const int r = idx >> 3;
            const int c = idx & 7;
            const uint32_t soff = (r * PAD + c * 4) * 4;
            cpasync16(sA + soff, Ag + (size_t)r * K + c * 4);
            cpasync16(sB + soff, Bg + (size_t)r * K + c * 4);
        }
        asm volatile("cp.async.commit_group;" ::: "memory");
    };

    float acc[4][4][4];
#pragma unroll
    for (int mf = 0; mf < 4; mf++)
#pragma unroll
        for (int nf = 0; nf < 4; nf++)
#pragma unroll
            for (int q = 0; q < 4; q++) acc[mf][nf][q] = 0.0f;

    load_chunk(0, 0);
    load_chunk(1, 1);

    int cs = 0;
    int ls = 2;
    for (int i = 0; i < nchunk; i++) {
        if (i + 1 < nchunk) {
            asm volatile("cp.async.wait_group 1;" ::: "memory");
        } else {
            asm volatile("cp.async.wait_group 0;" ::: "memory");
        }
        __syncthreads();

        const int j = i + 2;
        if (j < nchunk) {
            load_chunk(ls, j);
            ls = (ls == NSTAGE - 1) ? 0 : ls + 1;
        }

        const uint32_t stA = smem_u32 + (cs * STAGE_F) * 4;
        const uint32_t stB = stA + TILE_F * 4;
        const uint32_t aAddr = stA + ((wm * 64 + arow) * PAD + acsh) * 4;
        const uint32_t bAddr = stB + ((wn * 32 + brow) * PAD + bcsh) * 4;
        cs = (cs == NSTAGE - 1) ? 0 : cs + 1;

#pragma unroll
        for (int kk = 0; kk < 4; kk++) {
            const int k0 = kk * 8;
            uint32_t af[4][4];
#pragma unroll
            for (int mf = 0; mf < 4; mf++)
                ldsm_x4(af[mf], aAddr + (mf * 16 * PAD + k0) * 4);
            uint32_t bf[4][2];
#pragma unroll
            for (int np = 0; np < 2; np++) {
                uint32_t bt[4];
                ldsm_x4(bt, bAddr + (np * 16 * PAD + k0) * 4);
#pragma unroll
                for (int q = 0; q < 4; q++) bt[q] = rnau(bt[q]);
                bf[2 * np][0]     = bt[0]; bf[2 * np][1]     = bt[1];
                bf[2 * np + 1][0] = bt[2]; bf[2 * np + 1][1] = bt[3];
            }
#pragma unroll
            for (int mf = 0; mf < 4; mf++)
#pragma unroll
                for (int nf = 0; nf < 4; nf++)
                    mma_tf32(acc[mf][nf], af[mf], bf[nf]);
        }
    }

#pragma unroll
    for (int mf = 0; mf < 4; mf++) {
        const int row = bm + wm * 64 + mf * 16 + gid;
#pragma unroll
        for (int nf = 0; nf < 4; nf++) {
            const int col = bn + wn * 32 + nf * 8 + 2 * tig;
            const float b0 = bias[col], b1 = bias[col + 1];
            float2 v0, v1;
            v0.x = acc[mf][nf][0] + b0; v0.y = acc[mf][nf][1] + b1;
            v1.x = acc[mf][nf][2] + b0; v1.y = acc[mf][nf][3] + b1;
            *(float2*)&C[(size_t)row * N + col]       = v0;
            *(float2*)&C[(size_t)(row + 8) * N + col] = v1;
        }
    }
}

// =====================================================================
// Flash attention v5: paired q-blocks; Vt in swizzled 256B rows
// (VPAD=64, XOR f(row)=((row&7)^((row>>2)&7))<<4) — conflict-free
// transpose stores AND ldmatrix reads.
// =====================================================================
#define QT    128
#define KT    64
#define DPAD  132
#define VPAD  64
#define PPAD  68
#define KOFF  0
#define VOFF  (2 * KT * DPAD)                 // 16896
#define POFF  (VOFF + 2 * QT * VPAD)          // 33280
#define ATTN_F (POFF + QT * PPAD)             // 41984
#define ATTN_SMEM_BYTES (ATTN_F * 4)          // 167936
#define NQB   (SEQ / QT)                      // 16

__global__ __launch_bounds__(256, 1) void attn_tc_kernel(
    const float* __restrict__ QKV, float* __restrict__ Y)
{
    extern __shared__ float sm[];

    const int h    = blockIdx.y;
    const int pair = blockIdx.x;            // 0..7
    const int kvh  = h >> 2;
    const int tid  = threadIdx.x;
    const int wid  = tid >> 5;
    const int lane = tid & 31;
    const int gid  = lane >> 2;
    const int tig  = lane & 3;
    const int w16  = wid * 16;

    const int arow = lane & 15;
    const int acsh = (lane >> 4) * 4;
    const int brow = ((lane >> 4) << 3) + (lane & 7);
    const int bcsh = ((lane >> 3) & 1) * 4;

    const uint32_t smem_u32 = (uint32_t)__cvta_generic_to_shared(sm);

    const float* Qg = QKV + h * DK;
    const float* Kg = QKV + DMODEL + kvh * DK;
    const float* Vg = QKV + DMODEL + KVDIM + kvh * DK;

    const uint32_t kBase = smem_u32 + (KOFF + brow * DPAD + bcsh) * 4;
    const uint32_t vtRegion = smem_u32 + VOFF * 4;
    const uint32_t pAddr = smem_u32 + (POFF + (w16 + arow) * PPAD + acsh) * 4;
    float* Ps = sm + POFF;

    // Vt read swizzle components (per lane)
    const int b7  = brow & 7;
    const int bq2 = brow >> 2;
    const int bcsh4 = bcsh * 4;

    const int vbr0 = tid >> 5;
    const int vbc0 = tid & 31;
    const float scale = 0.08838834764831845f;

    auto issue_K = [&](int jbi, int buf) {
        const float* src = Kg + (size_t)(jbi * KT) * NQKV;
        const uint32_t dst = smem_u32 + (KOFF + buf * KT * DPAD) * 4;
#pragma unroll
        for (int it = 0; it < 8; it++) {
            const int idx = tid + it * 256;
            const int r = idx >> 5;
            const int c = idx & 31;
            cpasync16(dst + (r * DPAD + c * 4) * 4, src + (size_t)r * NQKV + c * 4);
        }
        asm volatile("cp.async.commit_group;" ::: "memory");
    };
    auto ldg_V = [&](int jbi, float4 vb[2][4]) {
        const float* src = Vg + (size_t)(jbi * KT) * NQKV;
#pragma unroll
        for (int b = 0; b < 2; b++) {
            const int br = vbr0 + b * 8;
#pragma unroll
            for (int j = 0; j < 4; j++)
                vb[b][j] = *(const float4*)&src[(size_t)(br * 4 + j) * NQKV + vbc0 * 4];
        }
    };
    // Transposed V store: Vt[row=d][col=key], 256B rows, XOR swizzle.
    auto sts_Vt = [&](int buf, float4 vb[2][4]) {
        char* vt = (char*)(sm + VOFF + buf * QT * VPAD);
#pragma unroll
        for (int b = 0; b < 2; b++) {
            const int br = vbr0 + b * 8;
            const float* v = (const float*)vb[b];
#pragma unroll
            for (int k = 0; k < 4; k++) {
                float4 w;
                w.x = v[0 * 4 + k]; w.y = v[1 * 4 + k];
                w.z = v[2 * 4 + k]; w.w = v[3 * 4 + k];
                const int row = vbc0 * 4 + k;
                uint32_t off = row * 256 + (br << 4);
                off ^= (uint32_t)(((row & 7) ^ ((row >> 2) & 7)) << 4);
                *(float4*)(vt + off) = w;
            }
        }
    };

    for (int half = 0; half < 2; half++) {
        const int qb = half ? pair : (NQB - 1 - pair);
        const int q0 = qb * QT;
        const int rg0 = q0 + w16 + gid;
        const int rg1 = rg0 + 8;
        const int njb = 2 * qb + 2;

        asm volatile("cp.async.wait_group 0;" ::: "memory");
        __syncthreads();

        // ---- stage Q (pre-rounded tf32) into K region, ldsm to regs ----
        for (int i = tid; i < QT * 32; i += 256) {
            const int r  = i >> 5;
            const int c4 = (i & 31) << 2;
            *(float4*)&sm[r * DPAD + c4] = *(const float4*)&Qg[(size_t)(q0 + r) * NQKV + c4];
        }
        __syncthreads();
        uint32_t qf[16][4];
        {
            const uint32_t qAddr = smem_u32 + ((w16 + arow) * DPAD + acsh) * 4;
#pragma unroll
            for (int kk = 0; kk < 16; kk++)
                ldsm_x4(qf[kk], qAddr + kk * 32);
        }
        __syncthreads();

        float o_acc[16][4];
#pragma unroll
        for (int nf = 0; nf < 16; nf++)
#pragma unroll
            for (int q = 0; q < 4; q++) o_acc[nf][q] = 0.0f;
        float m0 = -1e30f, m1 = -1e30f, l0 = 0.0f, l1 = 0.0f;

        issue_K(0, 0);
        {
            float4 vb[2][4];
            ldg_V(0, vb);
            sts_Vt(0, vb);
        }

        for (int jb = 0; jb < njb; jb++) {
            const int buf = jb & 1;

            asm volatile("cp.async.wait_group 0;" ::: "memory");
            __syncthreads();

            const bool have_next = (jb + 1 < njb);
            float4 vb[2][4];
            if (have_next) {
                issue_K(jb + 1, buf ^ 1);
                ldg_V(jb + 1, vb);
            }

            // ---- S = Q @ K^T ----
            float s[8][4];
#pragma unroll
            for (int nf = 0; nf < 8; nf++)
#pragma unroll
                for (int q = 0; q < 4; q++) s[nf][q] = 0.0f;

            const uint32_t kAddr = kBase + (buf * KT * DPAD) * 4;
#pragma unroll
            for (int kk = 0; kk < 16; kk++) {
                const int kd = kk * 8;
                uint32_t bf[8][2];
#pragma unroll
                for (int np = 0; np < 4; np++) {
                    uint32_t bt[4];
                    ldsm_x4(bt, kAddr + (np * 16 * DPAD + kd) * 4);
                    bf[2 * np][0]     = bt[0]; bf[2 * np][1]     = bt[1];
                    bf[2 * np + 1][0] = bt[2]; bf[2 * np + 1][1] = bt[3];
                }
#pragma unroll
                for (int nf = 0; nf < 8; nf++)
                    mma_tf32(s[nf], qf[kk], bf[nf]);
            }

            // ---- scale + mask + online softmax ----
            const int k0 = jb * KT;
            const bool need_mask = (jb >= 2 * qb);
            float mx0 = -1e30f, mx1 = -1e30f;
#pragma unroll
            for (int nf = 0; nf < 8; nf++) {
#pragma unroll
                for (int e = 0; e < 2; e++) {
                    const int jg = k0 + nf * 8 + 2 * tig + e;
                    float v0 = s[nf][e]     * scale;
                    float v1 = s[nf][2 + e] * scale;
                    if (need_mask) {
                        if (jg > rg0) v0 = -1e30f;
                        if (jg > rg1) v1 = -1e30f;
                    }
                    s[nf][e]     = v0;
                    s[nf][2 + e] = v1;
                    mx0 = fmaxf(mx0, v0);
                    mx1 = fmaxf(mx1, v1);
                }
            }
            mx0 = fmaxf(mx0, __shfl_xor_sync(0xffffffffu, mx0, 1));
            mx0 = fmaxf(mx0, __shfl_xor_sync(0xffffffffu, mx0, 2));
            mx1 = fmaxf(mx1, __shfl_xor_sync(0xffffffffu, mx1, 1));
            mx1 = fmaxf(mx1, __shfl_xor_sync(0xffffffffu, mx1, 2));

            const float mn0 = fmaxf(m0, mx0);
            const float mn1 = fmaxf(m1, mx1);
            const float al0 = __expf(m0 - mn0);
            const float al1 = __expf(m1 - mn1);
            m0 = mn0; m1 = mn1;

            float sum0 = 0.0f, sum1 = 0.0f;
#pragma unroll
            for (int nf = 0; nf < 8; nf++) {
                float p00 = __expf(s[nf][0] - mn0);
                float p01 = __expf(s[nf][1] - mn0);
                float p10 = __expf(s[nf][2] - mn1);
                float p11 = __expf(s[nf][3] - mn1);
                sum0 += p00 + p01;
                sum1 += p10 + p11;
                float2 w0; w0.x = rnaf(p00); w0.y = rnaf(p01);
                float2 w1; w1.x = rnaf(p10); w1.y = rnaf(p11);
                const int pc = nf * 8 + 2 * tig;
                *(float2*)&Ps[(w16 + gid)     * PPAD + pc] = w0;
                *(float2*)&Ps[(w16 + gid + 8) * PPAD + pc] = w1;
            }
            sum0 += __shfl_xor_sync(0xffffffffu, sum0, 1);
            sum0 += __shfl_xor_sync(0xffffffffu, sum0, 2);
            sum1 += __shfl_xor_sync(0xffffffffu, sum1, 1);
            sum1 += __shfl_xor_sync(0xffffffffu, sum1, 2);
            l0 = l0 * al0 + sum0;
            l1 = l1 * al1 + sum1;

#pragma unroll
            for (int nf = 0; nf < 16; nf++) {
                o_acc[nf][0] *= al0; o_acc[nf][1] *= al0;
                o_acc[nf][2] *= al1; o_acc[nf][3] *= al1;
            }

            if (have_next) sts_Vt(buf ^ 1, vb);
            __syncwarp();

            // ---- O += P @ V  (P + swizzled Vt via ldmatrix) ----
            const uint32_t vtBuf = vtRegion + buf * (QT * VPAD * 4);
#pragma unroll
            for (int kk = 0; kk < 8; kk++) {
                const int kb4 = kk * 32 + bcsh4;    // col byte within row
                uint32_t a[4];
                ldsm_x4(a, pAddr + kk * 32);
                uint32_t bf[16][2];
#pragma unroll
                for (int np = 0; np < 8; np++) {
                    const uint32_t sw = (uint32_t)((b7 ^ ((4 * np + bq2) & 7)) << 4);
                    uint32_t addr = vtBuf + (uint32_t)((np * 16 + brow) * 256) + kb4;
                    addr ^= sw;
                    uint32_t bt[4];
                    ldsm_x4(bt, addr);
                    bf[2 * np][0]     = bt[0]; bf[2 * np][1]     = bt[1];
                    bf[2 * np + 1][0] = bt[2]; bf[2 * np + 1][1] = bt[3];
                }
#pragma unroll
                for (int nf = 0; nf < 16; nf++)
                    mma_tf32(o_acc[nf], a, bf[nf]);
            }
        }

        // ---- epilogue for this half ----
        const float inv0 = 1.0f / l0;
        const float inv1 = 1.0f / l1;
#pragma unroll
        for (int nf = 0; nf < 16; nf++) {
            const int col = h * DK + nf * 8 + 2 * tig;
            float2 v0, v1;
            v0.x = rnaf(o_acc[nf][0] * inv0); v0.y = rnaf(o_acc[nf][1] * inv0);
            v1.x = rnaf(o_acc[nf][2] * inv1); v1.y = rnaf(o_acc[nf][3] * inv1);
            *(float2*)&Y[(size_t)rg0 * DMODEL + col] = v0;
            *(float2*)&Y[(size_t)rg1 * DMODEL + col] = v1;
        }
    }
}

// =====================================================================
// launch
// =====================================================================
extern "C" void kernel_launch(void* const* d_in, const int* in_sizes, int n_in,
                              void* d_out, int out_size)
{
    const float* x  = (const float*)d_in[0];
    const float* Wq = (const float*)d_in[1];
    const float* bq = (const float*)d_in[2];
    const float* Wk = (const float*)d_in[3];
    const float* bk = (const float*)d_in[4];
    const float* Wv = (const float*)d_in[5];
    const float* bv = (const float*)d_in[6];
    const float* Wo = (const float*)d_in[7];
    const float* bo = (const float*)d_in[8];
    float* out = (float*)d_out;

    float *QKVb, *Yb;
    cudaGetSymbolAddress((void**)&QKVb, g_QKV);
    cudaGetSymbolAddress((void**)&Yb,   g_Y);

    cudaFuncSetAttribute(gemm_qkv,
                         cudaFuncAttributeMaxDynamicSharedMemorySize, GEMM_SMEM_BYTES);
    cudaFuncSetAttribute(gemm_out,
                         cudaFuncAttributeMaxDynamicSharedMemorySize, GEMM_SMEM_BYTES);
    cudaFuncSetAttribute(attn_tc_kernel,
                         cudaFuncAttributeMaxDynamicSharedMemorySize, ATTN_SMEM_BYTES);

    dim3 blk(256);

    // fused QKV projection straight from raw inputs (in-register rounding)
    gemm_qkv<<<dim3(NQKV / 128, SEQ / 128), blk, GEMM_SMEM_BYTES>>>(
        x, Wq, Wk, Wv, bq, bk, bv, QKVb);

    attn_tc_kernel<<<dim3(NQB / 2, NHEADS), blk, ATTN_SMEM_BYTES>>>(QKVb, Yb);

    gemm_out<<<dim3(DMODEL / 128, SEQ / 128), blk, GEMM_SMEM_BYTES>>>(
        Yb, Wo, bo, out);
}

// round 14
// speedup vs baseline: 1.0631x; 1.0631x over previous
#include <cuda_runtime.h>
#include <cstdint>
#include <math.h>

// ---------------- problem constants ----------------
#define SEQ     2048
#define DMODEL  2048
#define KVDIM   512
#define NHEADS  16
#define DK      128
#define NQKV    (DMODEL + 2 * KVDIM)    // 3072

// ---------------- scratch ----------------
__device__ float g_QKV [SEQ * NQKV];
__device__ float g_Y   [SEQ * DMODEL];
__device__ float g_xt  [SEQ * DMODEL];
__device__ float g_Wqkv[NQKV * DMODEL];
__device__ float g_bqkv[NQKV];
__device__ float g_Wot [DMODEL * DMODEL];

// =====================================================================
// helpers
// =====================================================================
__device__ __forceinline__ float rnaf(float x) {
    uint32_t u;
    asm("cvt.rna.tf32.f32 %0, %1;" : "=r"(u) : "f"(x));
    return __uint_as_float(u);
}

__device__ __forceinline__ void cpasync16(uint32_t saddr, const void* gaddr) {
    asm volatile("cp.async.cg.shared.global [%0], [%1], 16;" :: "r"(saddr), "l"(gaddr) : "memory");
}

__device__ __forceinline__ void mma_tf32(float c[4], const uint32_t a[4], const uint32_t b[2]) {
    asm volatile(
        "mma.sync.aligned.m16n8k8.row.col.f32.tf32.tf32.f32 "
        "{%0,%1,%2,%3}, {%4,%5,%6,%7}, {%8,%9}, {%0,%1,%2,%3};"
        : "+f"(c[0]), "+f"(c[1]), "+f"(c[2]), "+f"(c[3])
        : "r"(a[0]), "r"(a[1]), "r"(a[2]), "r"(a[3]), "r"(b[0]), "r"(b[1]));
}

__device__ __forceinline__ void ldsm_x4(uint32_t r[4], uint32_t addr) {
    asm volatile("ldmatrix.sync.aligned.m8n8.x4.shared.b16 {%0,%1,%2,%3}, [%4];"
                 : "=r"(r[0]), "=r"(r[1]), "=r"(r[2]), "=r"(r[3]) : "r"(addr));
}

// =====================================================================
// fused tf32-rounding + bias-fusion pass
// =====================================================================
#define N4_BIG (SEQ * DMODEL / 4)
#define N4_KV  (KVDIM * DMODEL / 4)
#define CVT_TOTAL (3 * N4_BIG + 2 * N4_KV)

__global__ void cvt_all_kernel(
    const float4* __restrict__ x,  const float4* __restrict__ wq,
    const float4* __restrict__ wk, const float4* __restrict__ wv,
    const float4* __restrict__ wo,
    const float*  __restrict__ bq, const float* __restrict__ bk,
    const float*  __restrict__ bv,
    float4* __restrict__ xt, float4* __restrict__ wqkv,
    float4* __restrict__ wot, float* __restrict__ bqkv)
{
    int i = blockIdx.x * blockDim.x + threadIdx.x;
    if (i < CVT_TOTAL) {
        const float4* src;
        float4* dst;
        int j = i;
        if (j < N4_BIG)                    { src = x;  dst = xt; }
        else if ((j -= N4_BIG) < N4_BIG)   { src = wq; dst = wqkv; }
        else if ((j -= N4_BIG) < N4_KV)    { src = wk; dst = wqkv + N4_BIG; }
        else if ((j -= N4_KV)  < N4_KV)    { src = wv; dst = wqkv + N4_BIG + N4_KV; }
        else { j -= N4_KV;                   src = wo; dst = wot; }
        float4 v = src[j];
        float4 o;
        o.x = rnaf(v.x); o.y = rnaf(v.y); o.z = rnaf(v.z); o.w = rnaf(v.w);
        dst[j] = o;
    } else {
        int j = i - CVT_TOTAL;
        if (j < NQKV) {
            float v;
            if (j < DMODEL)              v = bq[j];
            else if (j < DMODEL + KVDIM) v = bk[j - DMODEL];
            else                         v = bv[j - DMODEL - KVDIM];
            bqkv[j] = v;
        }
    }
}

// =====================================================================
// tf32 mma.sync GEMM (proven config): CTA 128x128, 8 warps (2x4),
// warp tile 64x32, BK=32, 3-stage cp.async, 2 CTAs/SM.
// =====================================================================
#define BK      32
#define PAD     36
#define TILE_F  (128 * PAD)
#define STAGE_F (2 * TILE_F)
#define NSTAGE  3
#define GEMM_SMEM_BYTES (NSTAGE * STAGE_F * 4)

template <bool ROUND>
__global__ __launch_bounds__(256, 2) void gemm_tf32(
    const float* __restrict__ A, const float* __restrict__ B,
    const float* __restrict__ bias, float* __restrict__ C,
    int M, int N, int K)
{
    extern __shared__ float sm[];

    const int tid  = threadIdx.x;
    const int wid  = tid >> 5;
    const int lane = tid & 31;
    const int gid  = lane >> 2;
    const int tig  = lane & 3;
    const int wm   = wid >> 2;
    const int wn   = wid & 3;
    const int bm   = blockIdx.y * 128;
    const int bn   = blockIdx.x * 128;
    const int nchunk = K >> 5;

    const int arow = lane & 15;
    const int acsh = (lane >> 4) * 4;
    const int brow = ((lane >> 4) << 3) + (lane & 7);
    const int bcsh = ((lane >> 3) & 1) * 4;

    const uint32_t smem_u32 = (uint32_t)__cvta_generic_to_shared(sm);

    auto load_chunk = [&](int s, int j) {
        const uint32_t sA = smem_u32 + (s * STAGE_F) * 4;
        const uint32_t sB = sA + TILE_F * 4;
        const float* Ag = A + (size_t)bm * K + j * BK;
        const float* Bg = B + (size_t)bn * K + j * BK;
#pragma unroll
        for (int it = 0; it < 4; it++) {
            const int idx = tid + it * 256;
            const int r = idx >> 3;
            const int c = idx & 7;
            const uint32_t soff = (r * PAD + c * 4) * 4;
            cpasync16(sA + soff, Ag + (size_t)r * K + c * 4);
            cpasync16(sB + soff, Bg + (size_t)r * K + c * 4);
        }
        asm volatile("cp.async.commit_group;" ::: "memory");
    };

    float acc[4][4][4];
#pragma unroll
    for (int mf = 0; mf < 4; mf++)
#pragma unroll
        for (int nf = 0; nf < 4; nf++)
#pragma unroll
            for (int q = 0; q < 4; q++) acc[mf][nf][q] = 0.0f;

    load_chunk(0, 0);
    if (nchunk > 1) load_chunk(1, 1);

    int cs = 0;
    int ls = 2;
    for (int i = 0; i < nchunk; i++) {
        if (i + 1 < nchunk) {
            asm volatile("cp.async.wait_group 1;" ::: "memory");
        } else {
            asm volatile("cp.async.wait_group 0;" ::: "memory");
        }
        __syncthreads();

        const int j = i + 2;
        if (j < nchunk) {
            load_chunk(ls, j);
            ls = (ls == NSTAGE - 1) ? 0 : ls + 1;
        }

        const uint32_t stA = smem_u32 + (cs * STAGE_F) * 4;
        const uint32_t stB = stA + TILE_F * 4;
        const uint32_t aAddr = stA + ((wm * 64 + arow) * PAD + acsh) * 4;
        const uint32_t bAddr = stB + ((wn * 32 + brow) * PAD + bcsh) * 4;
        cs = (cs == NSTAGE - 1) ? 0 : cs + 1;

#pragma unroll
        for (int kk = 0; kk < 4; kk++) {
            const int k0 = kk * 8;
            uint32_t af[4][4];
#pragma unroll
            for (int mf = 0; mf < 4; mf++)
                ldsm_x4(af[mf], aAddr + (mf * 16 * PAD + k0) * 4);
            uint32_t bf[4][2];
#pragma unroll
            for (int np = 0; np < 2; np++) {
                uint32_t bt[4];
                ldsm_x4(bt, bAddr + (np * 16 * PAD + k0) * 4);
                bf[2 * np][0]     = bt[0]; bf[2 * np][1]     = bt[1];
                bf[2 * np + 1][0] = bt[2]; bf[2 * np + 1][1] = bt[3];
            }
#pragma unroll
            for (int mf = 0; mf < 4; mf++)
#pragma unroll
                for (int nf = 0; nf < 4; nf++)
                    mma_tf32(acc[mf][nf], af[mf], bf[nf]);
        }
    }

#pragma unroll
    for (int mf = 0; mf < 4; mf++) {
        const int row = bm + wm * 64 + mf * 16 + gid;
#pragma unroll
        for (int nf = 0; nf < 4; nf++) {
            const int col = bn + wn * 32 + nf * 8 + 2 * tig;
            const float b0 = bias[col], b1 = bias[col + 1];
            float2 v0, v1;
            if (ROUND) {
                v0.x = rnaf(acc[mf][nf][0] + b0); v0.y = rnaf(acc[mf][nf][1] + b1);
                v1.x = rnaf(acc[mf][nf][2] + b0); v1.y = rnaf(acc[mf][nf][3] + b1);
            } else {
                v0.x = acc[mf][nf][0] + b0; v0.y = acc[mf][nf][1] + b1;
                v1.x = acc[mf][nf][2] + b0; v1.y = acc[mf][nf][3] + b1;
            }
            *(float2*)&C[(size_t)row * N + col]       = v0;
            *(float2*)&C[(size_t)(row + 8) * N + col] = v1;
        }
    }
}

// =====================================================================
// QKV GEMM variant: CTA tile 128x192 (warp tile 64x48), BK=32,
// 2-stage cp.async, 2 CTAs/SM. Grid 16x16 = 256 CTAs = ONE wave.
// Output rna-rounded.
// =====================================================================
#define TBN     192
#define AT192_F (128 * PAD)
#define BT192_F (TBN * PAD)
#define STG192_F (AT192_F + BT192_F)
#define G192_SMEM_BYTES (2 * STG192_F * 4)

__global__ __launch_bounds__(256, 2) void gemm_tf32_n192(
    const float* __restrict__ A, const float* __restrict__ B,
    const float* __restrict__ bias, float* __restrict__ C,
    int M, int N, int K)
{
    extern __shared__ float sm[];

    const int tid  = threadIdx.x;
    const int wid  = tid >> 5;
    const int lane = tid & 31;
    const int gid  = lane >> 2;
    const int tig  = lane & 3;
    const int wm   = wid >> 2;
    const int wn   = wid & 3;
    const int bm   = blockIdx.y * 128;
    const int bn   = blockIdx.x * TBN;
    const int nchunk = K >> 5;

    const int arow = lane & 15;
    const int acsh = (lane >> 4) * 4;
    const int brow = ((lane >> 4) << 3) + (lane & 7);
    const int bcsh = ((lane >> 3) & 1) * 4;

    const uint32_t smem_u32 = (uint32_t)__cvta_generic_to_shared(sm);

    auto load_chunk = [&](int s, int j) {
        const uint32_t sA = smem_u32 + (s * STG192_F) * 4;
        const uint32_t sB = sA + AT192_F * 4;
        const float* Ag = A + (size_t)bm * K + j * BK;
        const float* Bg = B + (size_t)bn * K + j * BK;
#pragma unroll
        for (int it = 0; it < 4; it++) {
            const int idx = tid + it * 256;
            const int r = idx >> 3;
            const int c = idx & 7;
            cpasync16(sA + (r * PAD + c * 4) * 4, Ag + (size_t)r * K + c * 4);
        }
#pragma unroll
        for (int it = 0; it < 6; it++) {
            const int idx = tid + it * 256;
            const int r = idx >> 3;
            const int c = idx & 7;
            cpasync16(sB + (r * PAD + c * 4) * 4, Bg + (size_t)r * K + c * 4);
        }
        asm volatile("cp.async.commit_group;" ::: "memory");
    };

    float acc[4][6][4];
#pragma unroll
    for (int mf = 0; mf < 4; mf++)
#pragma unroll
        for (int nf = 0; nf < 6; nf++)
#pragma unroll
            for (int q = 0; q < 4; q++) acc[mf][nf][q] = 0.0f;

    load_chunk(0, 0);

    for (int i = 0; i < nchunk; i++) {
        if (i + 1 < nchunk) {
            load_chunk((i + 1) & 1, i + 1);
            asm volatile("cp.async.wait_group 1;" ::: "memory");
        } else {
            asm volatile("cp.async.wait_group 0;" ::: "memory");
        }
        __syncthreads();

        const uint32_t stA = smem_u32 + ((i & 1) * STG192_F) * 4;
        const uint32_t stB = stA + AT192_F * 4;
        const uint32_t aAddr = stA + ((wm * 64 + arow) * PAD + acsh) * 4;
        const uint32_t bAddr = stB + ((wn * 48 + brow) * PAD + bcsh) * 4;

#pragma unroll
        for (int kk = 0; kk < 4; kk++) {
            const int k0 = kk * 8;
            uint32_t af[4][4];
#pragma unroll
            for (int mf = 0; mf < 4; mf++)
                ldsm_x4(af[mf], aAddr + (mf * 16 * PAD + k0) * 4);
            uint32_t bf[6][2];
#pragma unroll
            for (int np = 0; np < 3; np++) {
                uint32_t bt[4];
                ldsm_x4(bt, bAddr + (np * 16 * PAD + k0) * 4);
                bf[2 * np][0]     = bt[0]; bf[2 * np][1]     = bt[1];
                bf[2 * np + 1][0] = bt[2]; bf[2 * np + 1][1] = bt[3];
            }
#pragma unroll
            for (int mf = 0; mf < 4; mf++)
#pragma unroll
                for (int nf = 0; nf < 6; nf++)
                    mma_tf32(acc[mf][nf], af[mf], bf[nf]);
        }
        __syncthreads();
    }

#pragma unroll
    for (int mf = 0; mf < 4; mf++) {
        const int row = bm + wm * 64 + mf * 16 + gid;
#pragma unroll
        for (int nf = 0; nf < 6; nf++) {
            const int col = bn + wn * 48 + nf * 8 + 2 * tig;
            const float b0 = bias[col], b1 = bias[col + 1];
            float2 v0, v1;
            v0.x = rnaf(acc[mf][nf][0] + b0); v0.y = rnaf(acc[mf][nf][1] + b1);
            v1.x = rnaf(acc[mf][nf][2] + b0); v1.y = rnaf(acc[mf][nf][3] + b1);
            *(float2*)&C[(size_t)row * N + col]       = v0;
            *(float2*)&C[(size_t)(row + 8) * N + col] = v1;
        }
    }
}

// =====================================================================
// Flash attention v5: paired q-blocks + swizzled Vt (VPAD=64, 256B rows,
// XOR f(row)=((row&7)^((row>>2)&7))<<4) — conflict-free transpose
// stores AND ldmatrix reads.
// =====================================================================
#define QT    128
#define KT    64
#define DPAD  132
#define VPAD  64
#define PPAD  68
#define KOFF  0
#define VOFF  (2 * KT * DPAD)                 // 16896
#define POFF  (VOFF + 2 * QT * VPAD)          // 33280
#define ATTN_F (POFF + QT * PPAD)             // 41984
#define ATTN_SMEM_BYTES (ATTN_F * 4)          // 167936
#define NQB   (SEQ / QT)                      // 16

__global__ __launch_bounds__(256, 1) void attn_tc_kernel(
    const float* __restrict__ QKV, float* __restrict__ Y)
{
    extern __shared__ float sm[];

    const int h    = blockIdx.y;
    const int pair = blockIdx.x;            // 0..7
    const int kvh  = h >> 2;
    const int tid  = threadIdx.x;
    const int wid  = tid >> 5;
    const int lane = tid & 31;
    const int gid  = lane >> 2;
    const int tig  = lane & 3;
    const int w16  = wid * 16;

    const int arow = lane & 15;
    const int acsh = (lane >> 4) * 4;
    const int brow = ((lane >> 4) << 3) + (lane & 7);
    const int bcsh = ((lane >> 3) & 1) * 4;

    const uint32_t smem_u32 = (uint32_t)__cvta_generic_to_shared(sm);

    const float* Qg = QKV + h * DK;
    const float* Kg = QKV + DMODEL + kvh * DK;
    const float* Vg = QKV + DMODEL + KVDIM + kvh * DK;

    const uint32_t kBase = smem_u32 + (KOFF + brow * DPAD + bcsh) * 4;
    const uint32_t vtRegion = smem_u32 + VOFF * 4;
    const uint32_t pAddr = smem_u32 + (POFF + (w16 + arow) * PPAD + acsh) * 4;
    float* Ps = sm + POFF;

    const int b7  = brow & 7;
    const int bq2 = brow >> 2;
    const int bcsh4 = bcsh * 4;

    const int vbr0 = tid >> 5;
    const int vbc0 = tid & 31;
    const float scale = 0.08838834764831845f;

    auto issue_K = [&](int jbi, int buf) {
        const float* src = Kg + (size_t)(jbi * KT) * NQKV;
        const uint32_t dst = smem_u32 + (KOFF + buf * KT * DPAD) * 4;
#pragma unroll
        for (int it = 0; it < 8; it++) {
            const int idx = tid + it * 256;
            const int r = idx >> 5;
            const int c = idx & 31;
            cpasync16(dst + (r * DPAD + c * 4) * 4, src + (size_t)r * NQKV + c * 4);
        }
        asm volatile("cp.async.commit_group;" ::: "memory");
    };
    auto ldg_V = [&](int jbi, float4 vb[2][4]) {
        const float* src = Vg + (size_t)(jbi * KT) * NQKV;
#pragma unroll
        for (int b = 0; b < 2; b++) {
            const int br = vbr0 + b * 8;
#pragma unroll
            for (int j = 0; j < 4; j++)
                vb[b][j] = *(const float4*)&src[(size_t)(br * 4 + j) * NQKV + vbc0 * 4];
        }
    };
    auto sts_Vt = [&](int buf, float4 vb[2][4]) {
        char* vt = (char*)(sm + VOFF + buf * QT * VPAD);
#pragma unroll
        for (int b = 0; b < 2; b++) {
            const int br = vbr0 + b * 8;
            const float* v = (const float*)vb[b];
#pragma unroll
            for (int k = 0; k < 4; k++) {
                float4 w;
                w.x = v[0 * 4 + k]; w.y = v[1 * 4 + k];
                w.z = v[2 * 4 + k]; w.w = v[3 * 4 + k];
                const int row = vbc0 * 4 + k;
                uint32_t off = row * 256 + (br << 4);
                off ^= (uint32_t)(((row & 7) ^ ((row >> 2) & 7)) << 4);
                *(float4*)(vt + off) = w;
            }
        }
    };

    for (int half = 0; half < 2; half++) {
        const int qb = half ? pair : (NQB - 1 - pair);
        const int q0 = qb * QT;
        const int rg0 = q0 + w16 + gid;
        const int rg1 = rg0 + 8;
        const int njb = 2 * qb + 2;

        asm volatile("cp.async.wait_group 0;" ::: "memory");
        __syncthreads();

        // ---- stage Q (pre-rounded tf32) into K region, ldsm to regs ----
        for (int i = tid; i < QT * 32; i += 256) {
            const int r  = i >> 5;
            const int c4 = (i & 31) << 2;
            *(float4*)&sm[r * DPAD + c4] = *(const float4*)&Qg[(size_t)(q0 + r) * NQKV + c4];
        }
        __syncthreads();
        uint32_t qf[16][4];
        {
            const uint32_t qAddr = smem_u32 + ((w16 + arow) * DPAD + acsh) * 4;
#pragma unroll
            for (int kk = 0; kk < 16; kk++)
                ldsm_x4(qf[kk], qAddr + kk * 32);
        }
        __syncthreads();

        float o_acc[16][4];
#pragma unroll
        for (int nf = 0; nf < 16; nf++)
#pragma unroll
            for (int q = 0; q < 4; q++) o_acc[nf][q] = 0.0f;
        float m0 = -1e30f, m1 = -1e30f, l0 = 0.0f, l1 = 0.0f;

        issue_K(0, 0);
        {
            float4 vb[2][4];
            ldg_V(0, vb);
            sts_Vt(0, vb);
        }

        for (int jb = 0; jb < njb; jb++) {
            const int buf = jb & 1;

            asm volatile("cp.async.wait_group 0;" ::: "memory");
            __syncthreads();

            const bool have_next = (jb + 1 < njb);
            float4 vb[2][4];
            if (have_next) {
                issue_K(jb + 1, buf ^ 1);
                ldg_V(jb + 1, vb);
            }

            // ---- S = Q @ K^T ----
            float s[8][4];
#pragma unroll
            for (int nf = 0; nf < 8; nf++)
#pragma unroll
                for (int q = 0; q < 4; q++) s[nf][q] = 0.0f;

            const uint32_t kAddr = kBase + (buf * KT * DPAD) * 4;
#pragma unroll
            for (int kk = 0; kk < 16; kk++) {
                const int kd = kk * 8;
                uint32_t bf[8][2];
#pragma unroll
                for (int np = 0; np < 4; np++) {
                    uint32_t bt[4];
                    ldsm_x4(bt, kAddr + (np * 16 * DPAD + kd) * 4);
                    bf[2 * np][0]     = bt[0]; bf[2 * np][1]     = bt[1];
                    bf[2 * np + 1][0] = bt[2]; bf[2 * np + 1][1] = bt[3];
                }
#pragma unroll
                for (int nf = 0; nf < 8; nf++)
                    mma_tf32(s[nf], qf[kk], bf[nf]);
            }

            // ---- scale + mask + online softmax ----
            const int k0 = jb * KT;
            const bool need_mask = (jb >= 2 * qb);
            float mx0 = -1e30f, mx1 = -1e30f;
#pragma unroll
            for (int nf = 0; nf < 8; nf++) {
#pragma unroll
                for (int e = 0; e < 2; e++) {
                    const int jg = k0 + nf * 8 + 2 * tig + e;
                    float v0 = s[nf][e]     * scale;
                    float v1 = s[nf][2 + e] * scale;
                    if (need_mask) {
                        if (jg > rg0) v0 = -1e30f;
                        if (jg > rg1) v1 = -1e30f;
                    }
                    s[nf][e]     = v0;
                    s[nf][2 + e] = v1;
                    mx0 = fmaxf(mx0, v0);
                    mx1 = fmaxf(mx1, v1);
                }
            }
            mx0 = fmaxf(mx0, __shfl_xor_sync(0xffffffffu, mx0, 1));
            mx0 = fmaxf(mx0, __shfl_xor_sync(0xffffffffu, mx0, 2));
            mx1 = fmaxf(mx1, __shfl_xor_sync(0xffffffffu, mx1, 1));
            mx1 = fmaxf(mx1, __shfl_xor_sync(0xffffffffu, mx1, 2));

            const float mn0 = fmaxf(m0, mx0);
            const float mn1 = fmaxf(m1, mx1);
            const float al0 = __expf(m0 - mn0);
            const float al1 = __expf(m1 - mn1);
            m0 = mn0; m1 = mn1;

            float sum0 = 0.0f, sum1 = 0.0f;
#pragma unroll
            for (int nf = 0; nf < 8; nf++) {
                float p00 = __expf(s[nf][0] - mn0);
                float p01 = __expf(s[nf][1] - mn0);
                float p10 = __expf(s[nf][2] - mn1);
                float p11 = __expf(s[nf][3] - mn1);
                sum0 += p00 + p01;
                sum1 += p10 + p11;
                float2 w0; w0.x = rnaf(p00); w0.y = rnaf(p01);
                float2 w1; w1.x = rnaf(p10); w1.y = rnaf(p11);
                const int pc = nf * 8 + 2 * tig;
                *(float2*)&Ps[(w16 + gid)     * PPAD + pc] = w0;
                *(float2*)&Ps[(w16 + gid + 8) * PPAD + pc] = w1;
            }
            sum0 += __shfl_xor_sync(0xffffffffu, sum0, 1);
            sum0 += __shfl_xor_sync(0xffffffffu, sum0, 2);
            sum1 += __shfl_xor_sync(0xffffffffu, sum1, 1);
            sum1 += __shfl_xor_sync(0xffffffffu, sum1, 2);
            l0 = l0 * al0 + sum0;
            l1 = l1 * al1 + sum1;

#pragma unroll
            for (int nf = 0; nf < 16; nf++) {
                o_acc[nf][0] *= al0; o_acc[nf][1] *= al0;
                o_acc[nf][2] *= al1; o_acc[nf][3] *= al1;
            }

            if (have_next) sts_Vt(buf ^ 1, vb);
            __syncwarp();

            // ---- O += P @ V  (P + swizzled Vt via ldmatrix) ----
            const uint32_t vtBuf = vtRegion + buf * (QT * VPAD * 4);
#pragma unroll
            for (int kk = 0; kk < 8; kk++) {
                const int kb4 = kk * 32 + bcsh4;
                uint32_t a[4];
                ldsm_x4(a, pAddr + kk * 32);
                uint32_t bf[16][2];
#pragma unroll
                for (int np = 0; np < 8; np++) {
                    const uint32_t sw = (uint32_t)((b7 ^ ((4 * np + bq2) & 7)) << 4);
                    uint32_t addr = vtBuf + (uint32_t)((np * 16 + brow) * 256) + kb4;
                    addr ^= sw;
                    uint32_t bt[4];
                    ldsm_x4(bt, addr);
                    bf[2 * np][0]     = bt[0]; bf[2 * np][1]     = bt[1];
                    bf[2 * np + 1][0] = bt[2]; bf[2 * np + 1][1] = bt[3];
                }
#pragma unroll
                for (int nf = 0; nf < 16; nf++)
                    mma_tf32(o_acc[nf], a, bf[nf]);
            }
        }

        // ---- epilogue for this half ----
        const float inv0 = 1.0f / l0;
        const float inv1 = 1.0f / l1;
#pragma unroll
        for (int nf = 0; nf < 16; nf++) {
            const int col = h * DK + nf * 8 + 2 * tig;
            float2 v0, v1;
            v0.x = rnaf(o_acc[nf][0] * inv0); v0.y = rnaf(o_acc[nf][1] * inv0);
            v1.x = rnaf(o_acc[nf][2] * inv1); v1.y = rnaf(o_acc[nf][3] * inv1);
            *(float2*)&Y[(size_t)rg0 * DMODEL + col] = v0;
            *(float2*)&Y[(size_t)rg1 * DMODEL + col] = v1;
        }
    }
}

// =====================================================================
// launch
// =====================================================================
extern "C" void kernel_launch(void* const* d_in, const int* in_sizes, int n_in,
                              void* d_out, int out_size)
{
    const float* x  = (const float*)d_in[0];
    const float* Wq = (const float*)d_in[1];
    const float* bq = (const float*)d_in[2];
    const float* Wk = (const float*)d_in[3];
    const float* bk = (const float*)d_in[4];
    const float* Wv = (const float*)d_in[5];
    const float* bv = (const float*)d_in[6];
    const float* Wo = (const float*)d_in[7];
    const float* bo = (const float*)d_in[8];
    float* out = (float*)d_out;

    float *QKVb, *Yb, *xt, *Wqkv, *bqkv, *Wot;
    cudaGetSymbolAddress((void**)&QKVb, g_QKV);
    cudaGetSymbolAddress((void**)&Yb,   g_Y);
    cudaGetSymbolAddress((void**)&xt,   g_xt);
    cudaGetSymbolAddress((void**)&Wqkv, g_Wqkv);
    cudaGetSymbolAddress((void**)&bqkv, g_bqkv);
    cudaGetSymbolAddress((void**)&Wot,  g_Wot);

    cudaFuncSetAttribute(gemm_tf32<false>,
                         cudaFuncAttributeMaxDynamicSharedMemorySize, GEMM_SMEM_BYTES);
    cudaFuncSetAttribute(gemm_tf32_n192,
                         cudaFuncAttributeMaxDynamicSharedMemorySize, G192_SMEM_BYTES);
    cudaFuncSetAttribute(attn_tc_kernel,
                         cudaFuncAttributeMaxDynamicSharedMemorySize, ATTN_SMEM_BYTES);

    dim3 blk(256);

    const int cvt_n = CVT_TOTAL + NQKV;
    cvt_all_kernel<<<(cvt_n + 255) / 256, 256>>>(
        (const float4*)x, (const float4*)Wq, (const float4*)Wk,
        (const float4*)Wv, (const float4*)Wo,
        bq, bk, bv,
        (float4*)xt, (float4*)Wqkv, (float4*)Wot, bqkv);

    // fused QKV projection: 128x192 tiles, 256 CTAs = one wave
    gemm_tf32_n192<<<dim3(NQKV / TBN, SEQ / 128), blk, G192_SMEM_BYTES>>>(
        xt, Wqkv, bqkv, QKVb, SEQ, NQKV, DMODEL);

    attn_tc_kernel<<<dim3(NQB / 2, NHEADS), blk, ATTN_SMEM_BYTES>>>(QKVb, Yb);

    gemm_tf32<false><<<dim3(DMODEL / 128, SEQ / 128), blk, GEMM_SMEM_BYTES>>>(
        Yb, Wot, bo, out, SEQ, DMODEL, DMODEL);
}

// round 15
// speedup vs baseline: 1.0838x; 1.0195x over previous
#include <cuda_runtime.h>
#include <cstdint>
#include <math.h>

// ---------------- problem constants ----------------
#define SEQ     2048
#define DMODEL  2048
#define KVDIM   512
#define NHEADS  16
#define DK      128
#define NQKV    (DMODEL + 2 * KVDIM)    // 3072

// ---------------- scratch ----------------
__device__ float g_QKV [SEQ * NQKV];
__device__ float g_Y   [SEQ * DMODEL];
__device__ float g_xt  [SEQ * DMODEL];
__device__ float g_Wqkv[NQKV * DMODEL];
__device__ float g_bqkv[NQKV];
__device__ float g_Wot [DMODEL * DMODEL];

// =====================================================================
// helpers
// =====================================================================
__device__ __forceinline__ float rnaf(float x) {
    uint32_t u;
    asm("cvt.rna.tf32.f32 %0, %1;" : "=r"(u) : "f"(x));
    return __uint_as_float(u);
}

__device__ __forceinline__ void cpasync16(uint32_t saddr, const void* gaddr) {
    asm volatile("cp.async.cg.shared.global [%0], [%1], 16;" :: "r"(saddr), "l"(gaddr) : "memory");
}

__device__ __forceinline__ void mma_tf32(float c[4], const uint32_t a[4], const uint32_t b[2]) {
    asm volatile(
        "mma.sync.aligned.m16n8k8.row.col.f32.tf32.tf32.f32 "
        "{%0,%1,%2,%3}, {%4,%5,%6,%7}, {%8,%9}, {%0,%1,%2,%3};"
        : "+f"(c[0]), "+f"(c[1]), "+f"(c[2]), "+f"(c[3])
        : "r"(a[0]), "r"(a[1]), "r"(a[2]), "r"(a[3]), "r"(b[0]), "r"(b[1]));
}

__device__ __forceinline__ void ldsm_x4(uint32_t r[4], uint32_t addr) {
    asm volatile("ldmatrix.sync.aligned.m8n8.x4.shared.b16 {%0,%1,%2,%3}, [%4];"
                 : "=r"(r[0]), "=r"(r[1]), "=r"(r[2]), "=r"(r[3]) : "r"(addr));
}

// =====================================================================
// fused tf32-rounding + bias-fusion pass
// =====================================================================
#define N4_BIG (SEQ * DMODEL / 4)
#define N4_KV  (KVDIM * DMODEL / 4)
#define CVT_TOTAL (3 * N4_BIG + 2 * N4_KV)

__global__ void cvt_all_kernel(
    const float4* __restrict__ x,  const float4* __restrict__ wq,
    const float4* __restrict__ wk, const float4* __restrict__ wv,
    const float4* __restrict__ wo,
    const float*  __restrict__ bq, const float* __restrict__ bk,
    const float*  __restrict__ bv,
    float4* __restrict__ xt, float4* __restrict__ wqkv,
    float4* __restrict__ wot, float* __restrict__ bqkv)
{
    int i = blockIdx.x * blockDim.x + threadIdx.x;
    if (i < CVT_TOTAL) {
        const float4* src;
        float4* dst;
        int j = i;
        if (j < N4_BIG)                    { src = x;  dst = xt; }
        else if ((j -= N4_BIG) < N4_BIG)   { src = wq; dst = wqkv; }
        else if ((j -= N4_BIG) < N4_KV)    { src = wk; dst = wqkv + N4_BIG; }
        else if ((j -= N4_KV)  < N4_KV)    { src = wv; dst = wqkv + N4_BIG + N4_KV; }
        else { j -= N4_KV;                   src = wo; dst = wot; }
        float4 v = src[j];
        float4 o;
        o.x = rnaf(v.x); o.y = rnaf(v.y); o.z = rnaf(v.z); o.w = rnaf(v.w);
        dst[j] = o;
    } else {
        int j = i - CVT_TOTAL;
        if (j < NQKV) {
            float v;
            if (j < DMODEL)              v = bq[j];
            else if (j < DMODEL + KVDIM) v = bk[j - DMODEL];
            else                         v = bv[j - DMODEL - KVDIM];
            bqkv[j] = v;
        }
    }
}

// =====================================================================
// tf32 mma.sync GEMM (proven config): CTA 128x128, 8 warps (2x4),
// warp tile 64x32, BK=32, 3-stage cp.async, 2 CTAs/SM.
// =====================================================================
#define BK      32
#define PAD     36
#define TILE_F  (128 * PAD)
#define STAGE_F (2 * TILE_F)
#define NSTAGE  3
#define GEMM_SMEM_BYTES (NSTAGE * STAGE_F * 4)

template <bool ROUND>
__global__ __launch_bounds__(256, 2) void gemm_tf32(
    const float* __restrict__ A, const float* __restrict__ B,
    const float* __restrict__ bias, float* __restrict__ C,
    int M, int N, int K)
{
    extern __shared__ float sm[];

    const int tid  = threadIdx.x;
    const int wid  = tid >> 5;
    const int lane = tid & 31;
    const int gid  = lane >> 2;
    const int tig  = lane & 3;
    const int wm   = wid >> 2;
    const int wn   = wid & 3;
    const int bm   = blockIdx.y * 128;
    const int bn   = blockIdx.x * 128;
    const int nchunk = K >> 5;

    const int arow = lane & 15;
    const int acsh = (lane >> 4) * 4;
    const int brow = ((lane >> 4) << 3) + (lane & 7);
    const int bcsh = ((lane >> 3) & 1) * 4;

    const uint32_t smem_u32 = (uint32_t)__cvta_generic_to_shared(sm);

    auto load_chunk = [&](int s, int j) {
        const uint32_t sA = smem_u32 + (s * STAGE_F) * 4;
        const uint32_t sB = sA + TILE_F * 4;
        const float* Ag = A + (size_t)bm * K + j * BK;
        const float* Bg = B + (size_t)bn * K + j * BK;
#pragma unroll
        for (int it = 0; it < 4; it++) {
            const int idx = tid + it * 256;
            const int r = idx >> 3;
            const int c = idx & 7;
            const uint32_t soff = (r * PAD + c * 4) * 4;
            cpasync16(sA + soff, Ag + (size_t)r * K + c * 4);
            cpasync16(sB + soff, Bg + (size_t)r * K + c * 4);
        }
        asm volatile("cp.async.commit_group;" ::: "memory");
    };

    float acc[4][4][4];
#pragma unroll
    for (int mf = 0; mf < 4; mf++)
#pragma unroll
        for (int nf = 0; nf < 4; nf++)
#pragma unroll
            for (int q = 0; q < 4; q++) acc[mf][nf][q] = 0.0f;

    load_chunk(0, 0);
    if (nchunk > 1) load_chunk(1, 1);

    int cs = 0;
    int ls = 2;
    for (int i = 0; i < nchunk; i++) {
        if (i + 1 < nchunk) {
            asm volatile("cp.async.wait_group 1;" ::: "memory");
        } else {
            asm volatile("cp.async.wait_group 0;" ::: "memory");
        }
        __syncthreads();

        const int j = i + 2;
        if (j < nchunk) {
            load_chunk(ls, j);
            ls = (ls == NSTAGE - 1) ? 0 : ls + 1;
        }

        const uint32_t stA = smem_u32 + (cs * STAGE_F) * 4;
        const uint32_t stB = stA + TILE_F * 4;
        const uint32_t aAddr = stA + ((wm * 64 + arow) * PAD + acsh) * 4;
        const uint32_t bAddr = stB + ((wn * 32 + brow) * PAD + bcsh) * 4;
        cs = (cs == NSTAGE - 1) ? 0 : cs + 1;

#pragma unroll
        for (int kk = 0; kk < 4; kk++) {
            const int k0 = kk * 8;
            uint32_t af[4][4];
#pragma unroll
            for (int mf = 0; mf < 4; mf++)
                ldsm_x4(af[mf], aAddr + (mf * 16 * PAD + k0) * 4);
            uint32_t bf[4][2];
#pragma unroll
            for (int np = 0; np < 2; np++) {
                uint32_t bt[4];
                ldsm_x4(bt, bAddr + (np * 16 * PAD + k0) * 4);
                bf[2 * np][0]     = bt[0]; bf[2 * np][1]     = bt[1];
                bf[2 * np + 1][0] = bt[2]; bf[2 * np + 1][1] = bt[3];
            }
#pragma unroll
            for (int mf = 0; mf < 4; mf++)
#pragma unroll
                for (int nf = 0; nf < 4; nf++)
                    mma_tf32(acc[mf][nf], af[mf], bf[nf]);
        }
    }

#pragma unroll
    for (int mf = 0; mf < 4; mf++) {
        const int row = bm + wm * 64 + mf * 16 + gid;
#pragma unroll
        for (int nf = 0; nf < 4; nf++) {
            const int col = bn + wn * 32 + nf * 8 + 2 * tig;
            const float b0 = bias[col], b1 = bias[col + 1];
            float2 v0, v1;
            if (ROUND) {
                v0.x = rnaf(acc[mf][nf][0] + b0); v0.y = rnaf(acc[mf][nf][1] + b1);
                v1.x = rnaf(acc[mf][nf][2] + b0); v1.y = rnaf(acc[mf][nf][3] + b1);
            } else {
                v0.x = acc[mf][nf][0] + b0; v0.y = acc[mf][nf][1] + b1;
                v1.x = acc[mf][nf][2] + b0; v1.y = acc[mf][nf][3] + b1;
            }
            *(float2*)&C[(size_t)row * N + col]       = v0;
            *(float2*)&C[(size_t)(row + 8) * N + col] = v1;
        }
    }
}

// =====================================================================
// QKV GEMM variant: CTA tile 128x192 (warp tile 64x48), BK=32,
// 2-stage cp.async, ONE sync per chunk, 2 CTAs/SM.
// Grid 16x16 = 256 CTAs = one wave. Output rna-rounded.
// =====================================================================
#define TBN     192
#define AT192_F (128 * PAD)
#define BT192_F (TBN * PAD)
#define STG192_F (AT192_F + BT192_F)
#define G192_SMEM_BYTES (2 * STG192_F * 4)

__global__ __launch_bounds__(256, 2) void gemm_tf32_n192(
    const float* __restrict__ A, const float* __restrict__ B,
    const float* __restrict__ bias, float* __restrict__ C,
    int M, int N, int K)
{
    extern __shared__ float sm[];

    const int tid  = threadIdx.x;
    const int wid  = tid >> 5;
    const int lane = tid & 31;
    const int gid  = lane >> 2;
    const int tig  = lane & 3;
    const int wm   = wid >> 2;
    const int wn   = wid & 3;
    const int bm   = blockIdx.y * 128;
    const int bn   = blockIdx.x * TBN;
    const int nchunk = K >> 5;

    const int arow = lane & 15;
    const int acsh = (lane >> 4) * 4;
    const int brow = ((lane >> 4) << 3) + (lane & 7);
    const int bcsh = ((lane >> 3) & 1) * 4;

    const uint32_t smem_u32 = (uint32_t)__cvta_generic_to_shared(sm);

    auto load_chunk = [&](int s, int j) {
        const uint32_t sA = smem_u32 + (s * STG192_F) * 4;
        const uint32_t sB = sA + AT192_F * 4;
        const float* Ag = A + (size_t)bm * K + j * BK;
        const float* Bg = B + (size_t)bn * K + j * BK;
#pragma unroll
        for (int it = 0; it < 4; it++) {
            const int idx = tid + it * 256;
            const int r = idx >> 3;
            const int c = idx & 7;
            cpasync16(sA + (r * PAD + c * 4) * 4, Ag + (size_t)r * K + c * 4);
        }
#pragma unroll
        for (int it = 0; it < 6; it++) {
            const int idx = tid + it * 256;
            const int r = idx >> 3;
            const int c = idx & 7;
            cpasync16(sB + (r * PAD + c * 4) * 4, Bg + (size_t)r * K + c * 4);
        }
        asm volatile("cp.async.commit_group;" ::: "memory");
    };

    float acc[4][6][4];
#pragma unroll
    for (int mf = 0; mf < 4; mf++)
#pragma unroll
        for (int nf = 0; nf < 6; nf++)
#pragma unroll
            for (int q = 0; q < 4; q++) acc[mf][nf][q] = 0.0f;

    load_chunk(0, 0);

    for (int i = 0; i < nchunk; i++) {
        // chunk i (sole group in flight) must be complete
        asm volatile("cp.async.wait_group 0;" ::: "memory");
        __syncthreads();   // also: stage (i+1)&1 free (computed at i-1)

        if (i + 1 < nchunk) load_chunk((i + 1) & 1, i + 1);

        const uint32_t stA = smem_u32 + ((i & 1) * STG192_F) * 4;
        const uint32_t stB = stA + AT192_F * 4;
        const uint32_t aAddr = stA + ((wm * 64 + arow) * PAD + acsh) * 4;
        const uint32_t bAddr = stB + ((wn * 48 + brow) * PAD + bcsh) * 4;

#pragma unroll
        for (int kk = 0; kk < 4; kk++) {
            const int k0 = kk * 8;
            uint32_t af[4][4];
#pragma unroll
            for (int mf = 0; mf < 4; mf++)
                ldsm_x4(af[mf], aAddr + (mf * 16 * PAD + k0) * 4);
            uint32_t bf[6][2];
#pragma unroll
            for (int np = 0; np < 3; np++) {
                uint32_t bt[4];
                ldsm_x4(bt, bAddr + (np * 16 * PAD + k0) * 4);
                bf[2 * np][0]     = bt[0]; bf[2 * np][1]     = bt[1];
                bf[2 * np + 1][0] = bt[2]; bf[2 * np + 1][1] = bt[3];
            }
#pragma unroll
            for (int mf = 0; mf < 4; mf++)
#pragma unroll
                for (int nf = 0; nf < 6; nf++)
                    mma_tf32(acc[mf][nf], af[mf], bf[nf]);
        }
    }

#pragma unroll
    for (int mf = 0; mf < 4; mf++) {
        const int row = bm + wm * 64 + mf * 16 + gid;
#pragma unroll
        for (int nf = 0; nf < 6; nf++) {
            const int col = bn + wn * 48 + nf * 8 + 2 * tig;
            const float b0 = bias[col], b1 = bias[col + 1];
            float2 v0, v1;
            v0.x = rnaf(acc[mf][nf][0] + b0); v0.y = rnaf(acc[mf][nf][1] + b1);
            v1.x = rnaf(acc[mf][nf][2] + b0); v1.y = rnaf(acc[mf][nf][3] + b1);
            *(float2*)&C[(size_t)row * N + col]       = v0;
            *(float2*)&C[(size_t)(row + 8) * N + col] = v1;
        }
    }
}

// =====================================================================
// Flash attention v6: LPT static schedule (makespan 32 tiles) +
// swizzled Vt. Grid (9 slots, 16 heads) = 144 CTAs, one wave.
//   slot 0      : {15}             (32 tiles)
//   slot 1..7   : {15-s, s-1}      (32 tiles)
//   slot 8      : {7}              (16 tiles)
// =====================================================================
#define QT    128
#define KT    64
#define DPAD  132
#define VPAD  64
#define PPAD  68
#define KOFF  0
#define VOFF  (2 * KT * DPAD)
#define POFF  (VOFF + 2 * QT * VPAD)
#define ATTN_F (POFF + QT * PPAD)
#define ATTN_SMEM_BYTES (ATTN_F * 4)
#define NQB   (SEQ / QT)                      // 16

__global__ __launch_bounds__(256, 1) void attn_tc_kernel(
    const float* __restrict__ QKV, float* __restrict__ Y)
{
    extern __shared__ float sm[];

    const int h    = blockIdx.y;
    const int slot = blockIdx.x;            // 0..8
    const int kvh  = h >> 2;
    const int tid  = threadIdx.x;
    const int wid  = tid >> 5;
    const int lane = tid & 31;
    const int gid  = lane >> 2;
    const int tig  = lane & 3;
    const int w16  = wid * 16;

    // static LPT job list
    int qlist[2];
    int nq;
    if (slot == 0)      { qlist[0] = NQB - 1; nq = 1; }
    else if (slot <= 7) { qlist[0] = NQB - 1 - slot; qlist[1] = slot - 1; nq = 2; }
    else                { qlist[0] = NQB / 2 - 1; nq = 1; }

    const int arow = lane & 15;
    const int acsh = (lane >> 4) * 4;
    const int brow = ((lane >> 4) << 3) + (lane & 7);
    const int bcsh = ((lane >> 3) & 1) * 4;

    const uint32_t smem_u32 = (uint32_t)__cvta_generic_to_shared(sm);

    const float* Qg = QKV + h * DK;
    const float* Kg = QKV + DMODEL + kvh * DK;
    const float* Vg = QKV + DMODEL + KVDIM + kvh * DK;

    const uint32_t kBase = smem_u32 + (KOFF + brow * DPAD + bcsh) * 4;
    const uint32_t vtRegion = smem_u32 + VOFF * 4;
    const uint32_t pAddr = smem_u32 + (POFF + (w16 + arow) * PPAD + acsh) * 4;
    float* Ps = sm + POFF;

    const int b7  = brow & 7;
    const int bq2 = brow >> 2;
    const int bcsh4 = bcsh * 4;

    const int vbr0 = tid >> 5;
    const int vbc0 = tid & 31;
    const float scale = 0.08838834764831845f;

    auto issue_K = [&](int jbi, int buf) {
        const float* src = Kg + (size_t)(jbi * KT) * NQKV;
        const uint32_t dst = smem_u32 + (KOFF + buf * KT * DPAD) * 4;
#pragma unroll
        for (int it = 0; it < 8; it++) {
            const int idx = tid + it * 256;
            const int r = idx >> 5;
            const int c = idx & 31;
            cpasync16(dst + (r * DPAD + c * 4) * 4, src + (size_t)r * NQKV + c * 4);
        }
        asm volatile("cp.async.commit_group;" ::: "memory");
    };
    auto ldg_V = [&](int jbi, float4 vb[2][4]) {
        const float* src = Vg + (size_t)(jbi * KT) * NQKV;
#pragma unroll
        for (int b = 0; b < 2; b++) {
            const int br = vbr0 + b * 8;
#pragma unroll
            for (int j = 0; j < 4; j++)
                vb[b][j] = *(const float4*)&src[(size_t)(br * 4 + j) * NQKV + vbc0 * 4];
        }
    };
    auto sts_Vt = [&](int buf, float4 vb[2][4]) {
        char* vt = (char*)(sm + VOFF + buf * QT * VPAD);
#pragma unroll
        for (int b = 0; b < 2; b++) {
            const int br = vbr0 + b * 8;
            const float* v = (const float*)vb[b];
#pragma unroll
            for (int k = 0; k < 4; k++) {
                float4 w;
                w.x = v[0 * 4 + k]; w.y = v[1 * 4 + k];
                w.z = v[2 * 4 + k]; w.w = v[3 * 4 + k];
                const int row = vbc0 * 4 + k;
                uint32_t off = row * 256 + (br << 4);
                off ^= (uint32_t)(((row & 7) ^ ((row >> 2) & 7)) << 4);
                *(float4*)(vt + off) = w;
            }
        }
    };

    for (int hi = 0; hi < nq; hi++) {
        const int qb = qlist[hi];
        const int q0 = qb * QT;
        const int rg0 = q0 + w16 + gid;
        const int rg1 = rg0 + 8;
        const int njb = 2 * qb + 2;

        asm volatile("cp.async.wait_group 0;" ::: "memory");
        __syncthreads();

        // ---- stage Q (pre-rounded tf32) into K region, ldsm to regs ----
        for (int i = tid; i < QT * 32; i += 256) {
            const int r  = i >> 5;
            const int c4 = (i & 31) << 2;
            *(float4*)&sm[r * DPAD + c4] = *(const float4*)&Qg[(size_t)(q0 + r) * NQKV + c4];
        }
        __syncthreads();
        uint32_t qf[16][4];
        {
            const uint32_t qAddr = smem_u32 + ((w16 + arow) * DPAD + acsh) * 4;
#pragma unroll
            for (int kk = 0; kk < 16; kk++)
                ldsm_x4(qf[kk], qAddr + kk * 32);
        }
        __syncthreads();

        float o_acc[16][4];
#pragma unroll
        for (int nf = 0; nf < 16; nf++)
#pragma unroll
            for (int q = 0; q < 4; q++) o_acc[nf][q] = 0.0f;
        float m0 = -1e30f, m1 = -1e30f, l0 = 0.0f, l1 = 0.0f;

        issue_K(0, 0);
        {
            float4 vb[2][4];
            ldg_V(0, vb);
            sts_Vt(0, vb);
        }

        for (int jb = 0; jb < njb; jb++) {
            const int buf = jb & 1;

            asm volatile("cp.async.wait_group 0;" ::: "memory");
            __syncthreads();

            const bool have_next = (jb + 1 < njb);
            float4 vb[2][4];
            if (have_next) {
                issue_K(jb + 1, buf ^ 1);
                ldg_V(jb + 1, vb);
            }

            // ---- S = Q @ K^T ----
            float s[8][4];
#pragma unroll
            for (int nf = 0; nf < 8; nf++)
#pragma unroll
                for (int q = 0; q < 4; q++) s[nf][q] = 0.0f;

            const uint32_t kAddr = kBase + (buf * KT * DPAD) * 4;
#pragma unroll
            for (int kk = 0; kk < 16; kk++) {
                const int kd = kk * 8;
                uint32_t bf[8][2];
#pragma unroll
                for (int np = 0; np < 4; np++) {
                    uint32_t bt[4];
                    ldsm_x4(bt, kAddr + (np * 16 * DPAD + kd) * 4);
                    bf[2 * np][0]     = bt[0]; bf[2 * np][1]     = bt[1];
                    bf[2 * np + 1][0] = bt[2]; bf[2 * np + 1][1] = bt[3];
                }
#pragma unroll
                for (int nf = 0; nf < 8; nf++)
                    mma_tf32(s[nf], qf[kk], bf[nf]);
            }

            // ---- scale + mask + online softmax ----
            const int k0 = jb * KT;
            const bool need_mask = (jb >= 2 * qb);
            float mx0 = -1e30f, mx1 = -1e30f;
#pragma unroll
            for (int nf = 0; nf < 8; nf++) {
#pragma unroll
                for (int e = 0; e < 2; e++) {
                    const int jg = k0 + nf * 8 + 2 * tig + e;
                    float v0 = s[nf][e]     * scale;
                    float v1 = s[nf][2 + e] * scale;
                    if (need_mask) {
                        if (jg > rg0) v0 = -1e30f;
                        if (jg > rg1) v1 = -1e30f;
                    }
                    s[nf][e]     = v0;
                    s[nf][2 + e] = v1;
                    mx0 = fmaxf(mx0, v0);
                    mx1 = fmaxf(mx1, v1);
                }
            }
            mx0 = fmaxf(mx0, __shfl_xor_sync(0xffffffffu, mx0, 1));
            mx0 = fmaxf(mx0, __shfl_xor_sync(0xffffffffu, mx0, 2));
            mx1 = fmaxf(mx1, __shfl_xor_sync(0xffffffffu, mx1, 1));
            mx1 = fmaxf(mx1, __shfl_xor_sync(0xffffffffu, mx1, 2));

            const float mn0 = fmaxf(m0, mx0);
            const float mn1 = fmaxf(m1, mx1);
            const float al0 = __expf(m0 - mn0);
            const float al1 = __expf(m1 - mn1);
            m0 = mn0; m1 = mn1;

            float sum0 = 0.0f, sum1 = 0.0f;
#pragma unroll
            for (int nf = 0; nf < 8; nf++) {
                float p00 = __expf(s[nf][0] - mn0);
                float p01 = __expf(s[nf][1] - mn0);
                float p10 = __expf(s[nf][2] - mn1);
                float p11 = __expf(s[nf][3] - mn1);
                sum0 += p00 + p01;
                sum1 += p10 + p11;
                float2 w0; w0.x = rnaf(p00); w0.y = rnaf(p01);
                float2 w1; w1.x = rnaf(p10); w1.y = rnaf(p11);
                const int pc = nf * 8 + 2 * tig;
                *(float2*)&Ps[(w16 + gid)     * PPAD + pc] = w0;
                *(float2*)&Ps[(w16 + gid + 8) * PPAD + pc] = w1;
            }
            sum0 += __shfl_xor_sync(0xffffffffu, sum0, 1);
            sum0 += __shfl_xor_sync(0xffffffffu, sum0, 2);
            sum1 += __shfl_xor_sync(0xffffffffu, sum1, 1);
            sum1 += __shfl_xor_sync(0xffffffffu, sum1, 2);
            l0 = l0 * al0 + sum0;
            l1 = l1 * al1 + sum1;

#pragma unroll
            for (int nf = 0; nf < 16; nf++) {
                o_acc[nf][0] *= al0; o_acc[nf][1] *= al0;
                o_acc[nf][2] *= al1; o_acc[nf][3] *= al1;
            }

            if (have_next) sts_Vt(buf ^ 1, vb);
            __syncwarp();

            // ---- O += P @ V  (P + swizzled Vt via ldmatrix) ----
            const uint32_t vtBuf = vtRegion + buf * (QT * VPAD * 4);
#pragma unroll
            for (int kk = 0; kk < 8; kk++) {
                const int kb4 = kk * 32 + bcsh4;
                uint32_t a[4];
                ldsm_x4(a, pAddr + kk * 32);
                uint32_t bf[16][2];
#pragma unroll
                for (int np = 0; np < 8; np++) {
                    const uint32_t sw = (uint32_t)((b7 ^ ((4 * np + bq2) & 7)) << 4);
                    uint32_t addr = vtBuf + (uint32_t)((np * 16 + brow) * 256) + kb4;
                    addr ^= sw;
                    uint32_t bt[4];
                    ldsm_x4(bt, addr);
                    bf[2 * np][0]     = bt[0]; bf[2 * np][1]     = bt[1];
                    bf[2 * np + 1][0] = bt[2]; bf[2 * np + 1][1] = bt[3];
                }
#pragma unroll
                for (int nf = 0; nf < 16; nf++)
                    mma_tf32(o_acc[nf], a, bf[nf]);
            }
        }

        // ---- epilogue for this job ----
        const float inv0 = 1.0f / l0;
        const float inv1 = 1.0f / l1;
#pragma unroll
        for (int nf = 0; nf < 16; nf++) {
            const int col = h * DK + nf * 8 + 2 * tig;
            float2 v0, v1;
            v0.x = rnaf(o_acc[nf][0] * inv0); v0.y = rnaf(o_acc[nf][1] * inv0);
            v1.x = rnaf(o_acc[nf][2] * inv1); v1.y = rnaf(o_acc[nf][3] * inv1);
            *(float2*)&Y[(size_t)rg0 * DMODEL + col] = v0;
            *(float2*)&Y[(size_t)rg1 * DMODEL + col] = v1;
        }
    }
}

// =====================================================================
// launch
// =====================================================================
extern "C" void kernel_launch(void* const* d_in, const int* in_sizes, int n_in,
                              void* d_out, int out_size)
{
    const float* x  = (const float*)d_in[0];
    const float* Wq = (const float*)d_in[1];
    const float* bq = (const float*)d_in[2];
    const float* Wk = (const float*)d_in[3];
    const float* bk = (const float*)d_in[4];
    const float* Wv = (const float*)d_in[5];
    const float* bv = (const float*)d_in[6];
    const float* Wo = (const float*)d_in[7];
    const float* bo = (const float*)d_in[8];
    float* out = (float*)d_out;

    float *QKVb, *Yb, *xt, *Wqkv, *bqkv, *Wot;
    cudaGetSymbolAddress((void**)&QKVb, g_QKV);
    cudaGetSymbolAddress((void**)&Yb,   g_Y);
    cudaGetSymbolAddress((void**)&xt,   g_xt);
    cudaGetSymbolAddress((void**)&Wqkv, g_Wqkv);
    cudaGetSymbolAddress((void**)&bqkv, g_bqkv);
    cudaGetSymbolAddress((void**)&Wot,  g_Wot);

    cudaFuncSetAttribute(gemm_tf32<false>,
                         cudaFuncAttributeMaxDynamicSharedMemorySize, GEMM_SMEM_BYTES);
    cudaFuncSetAttribute(gemm_tf32_n192,
                         cudaFuncAttributeMaxDynamicSharedMemorySize, G192_SMEM_BYTES);
    cudaFuncSetAttribute(attn_tc_kernel,
                         cudaFuncAttributeMaxDynamicSharedMemorySize, ATTN_SMEM_BYTES);

    dim3 blk(256);

    const int cvt_n = CVT_TOTAL + NQKV;
    cvt_all_kernel<<<(cvt_n + 255) / 256, 256>>>(
        (const float4*)x, (const float4*)Wq, (const float4*)Wk,
        (const float4*)Wv, (const float4*)Wo,
        bq, bk, bv,
        (float4*)xt, (float4*)Wqkv, (float4*)Wot, bqkv);

    // fused QKV projection: 128x192 tiles, 256 CTAs = one wave
    gemm_tf32_n192<<<dim3(NQKV / TBN, SEQ / 128), blk, G192_SMEM_BYTES>>>(
        xt, Wqkv, bqkv, QKVb, SEQ, NQKV, DMODEL);

    // attention: LPT schedule, 144 CTAs, one wave
    attn_tc_kernel<<<dim3(9, NHEADS), blk, ATTN_SMEM_BYTES>>>(QKVb, Yb);

    gemm_tf32<false><<<dim3(DMODEL / 128, SEQ / 128), blk, GEMM_SMEM_BYTES>>>(
        Yb, Wot, bo, out, SEQ, DMODEL, DMODEL);
}

// round 16
// speedup vs baseline: 1.0950x; 1.0104x over previous
#include <cuda_runtime.h>
#include <cstdint>
#include <math.h>

// ---------------- problem constants ----------------
#define SEQ     2048
#define DMODEL  2048
#define KVDIM   512
#define NHEADS  16
#define DK      128
#define NQKV    (DMODEL + 2 * KVDIM)    // 3072

// ---------------- scratch ----------------
__device__ float g_QKV [SEQ * NQKV];
__device__ float g_Y   [SEQ * DMODEL];
__device__ float g_xt  [SEQ * DMODEL];
__device__ float g_Wqkv[NQKV * DMODEL];
__device__ float g_bqkv[NQKV];
__device__ float g_Wot [DMODEL * DMODEL];

// =====================================================================
// helpers
// =====================================================================
__device__ __forceinline__ float rnaf(float x) {
    uint32_t u;
    asm("cvt.rna.tf32.f32 %0, %1;" : "=r"(u) : "f"(x));
    return __uint_as_float(u);
}

__device__ __forceinline__ void cpasync16(uint32_t saddr, const void* gaddr) {
    asm volatile("cp.async.cg.shared.global [%0], [%1], 16;" :: "r"(saddr), "l"(gaddr) : "memory");
}

__device__ __forceinline__ void mma_tf32(float c[4], const uint32_t a[4], const uint32_t b[2]) {
    asm volatile(
        "mma.sync.aligned.m16n8k8.row.col.f32.tf32.tf32.f32 "
        "{%0,%1,%2,%3}, {%4,%5,%6,%7}, {%8,%9}, {%0,%1,%2,%3};"
        : "+f"(c[0]), "+f"(c[1]), "+f"(c[2]), "+f"(c[3])
        : "r"(a[0]), "r"(a[1]), "r"(a[2]), "r"(a[3]), "r"(b[0]), "r"(b[1]));
}

__device__ __forceinline__ void ldsm_x4(uint32_t r[4], uint32_t addr) {
    asm volatile("ldmatrix.sync.aligned.m8n8.x4.shared.b16 {%0,%1,%2,%3}, [%4];"
                 : "=r"(r[0]), "=r"(r[1]), "=r"(r[2]), "=r"(r[3]) : "r"(addr));
}

// =====================================================================
// tf32-rounding for x, Wq, Wk, Wv + bias fusion (grid-stride).
// Wo is handled inside the QKV GEMM launch (hidden under its shadow).
// =====================================================================
#define N4_BIG (SEQ * DMODEL / 4)
#define N4_KV  (KVDIM * DMODEL / 4)
#define CVT2_TOTAL (2 * N4_BIG + 2 * N4_KV)

__global__ void cvt_all_kernel(
    const float4* __restrict__ x,  const float4* __restrict__ wq,
    const float4* __restrict__ wk, const float4* __restrict__ wv,
    const float*  __restrict__ bq, const float* __restrict__ bk,
    const float*  __restrict__ bv,
    float4* __restrict__ xt, float4* __restrict__ wqkv,
    float* __restrict__ bqkv)
{
    const int total = CVT2_TOTAL + NQKV;
    for (int i = blockIdx.x * blockDim.x + threadIdx.x; i < total;
         i += gridDim.x * blockDim.x) {
        if (i < CVT2_TOTAL) {
            const float4* src;
            float4* dst;
            int j = i;
            if (j < N4_BIG)                   { src = x;  dst = xt; }
            else if ((j -= N4_BIG) < N4_BIG)  { src = wq; dst = wqkv; }
            else if ((j -= N4_BIG) < N4_KV)   { src = wk; dst = wqkv + N4_BIG; }
            else { j -= N4_KV;                  src = wv; dst = wqkv + N4_BIG + N4_KV; }
            float4 v = src[j];
            float4 o;
            o.x = rnaf(v.x); o.y = rnaf(v.y); o.z = rnaf(v.z); o.w = rnaf(v.w);
            dst[j] = o;
        } else {
            int j = i - CVT2_TOTAL;
            float v;
            if (j < DMODEL)              v = bq[j];
            else if (j < DMODEL + KVDIM) v = bk[j - DMODEL];
            else                         v = bv[j - DMODEL - KVDIM];
            bqkv[j] = v;
        }
    }
}

// =====================================================================
// tf32 mma.sync GEMM (proven config): CTA 128x128, 8 warps (2x4),
// warp tile 64x32, BK=32, 3-stage cp.async, 2 CTAs/SM.
// =====================================================================
#define BK      32
#define PAD     36
#define TILE_F  (128 * PAD)
#define STAGE_F (2 * TILE_F)
#define NSTAGE  3
#define GEMM_SMEM_BYTES (NSTAGE * STAGE_F * 4)

template <bool ROUND>
__global__ __launch_bounds__(256, 2) void gemm_tf32(
    const float* __restrict__ A, const float* __restrict__ B,
    const float* __restrict__ bias, float* __restrict__ C,
    int M, int N, int K)
{
    extern __shared__ float sm[];

    const int tid  = threadIdx.x;
    const int wid  = tid >> 5;
    const int lane = tid & 31;
    const int gid  = lane >> 2;
    const int tig  = lane & 3;
    const int wm   = wid >> 2;
    const int wn   = wid & 3;
    const int bm   = blockIdx.y * 128;
    const int bn   = blockIdx.x * 128;
    const int nchunk = K >> 5;

    const int arow = lane & 15;
    const int acsh = (lane >> 4) * 4;
    const int brow = ((lane >> 4) << 3) + (lane & 7);
    const int bcsh = ((lane >> 3) & 1) * 4;

    const uint32_t smem_u32 = (uint32_t)__cvta_generic_to_shared(sm);

    auto load_chunk = [&](int s, int j) {
        const uint32_t sA = smem_u32 + (s * STAGE_F) * 4;
        const uint32_t sB = sA + TILE_F * 4;
        const float* Ag = A + (size_t)bm * K + j * BK;
        const float* Bg = B + (size_t)bn * K + j * BK;
#pragma unroll
        for (int it = 0; it < 4; it++) {
            const int idx = tid + it * 256;
            const int r = idx >> 3;
            const int c = idx & 7;
            const uint32_t soff = (r * PAD + c * 4) * 4;
            cpasync16(sA + soff, Ag + (size_t)r * K + c * 4);
            cpasync16(sB + soff, Bg + (size_t)r * K + c * 4);
        }
        asm volatile("cp.async.commit_group;" ::: "memory");
    };

    float acc[4][4][4];
#pragma unroll
    for (int mf = 0; mf < 4; mf++)
#pragma unroll
        for (int nf = 0; nf < 4; nf++)
#pragma unroll
            for (int q = 0; q < 4; q++) acc[mf][nf][q] = 0.0f;

    load_chunk(0, 0);
    if (nchunk > 1) load_chunk(1, 1);

    int cs = 0;
    int ls = 2;
    for (int i = 0; i < nchunk; i++) {
        if (i + 1 < nchunk) {
            asm volatile("cp.async.wait_group 1;" ::: "memory");
        } else {
            asm volatile("cp.async.wait_group 0;" ::: "memory");
        }
        __syncthreads();

        const int j = i + 2;
        if (j < nchunk) {
            load_chunk(ls, j);
            ls = (ls == NSTAGE - 1) ? 0 : ls + 1;
        }

        const uint32_t stA = smem_u32 + (cs * STAGE_F) * 4;
        const uint32_t stB = stA + TILE_F * 4;
        const uint32_t aAddr = stA + ((wm * 64 + arow) * PAD + acsh) * 4;
        const uint32_t bAddr = stB + ((wn * 32 + brow) * PAD + bcsh) * 4;
        cs = (cs == NSTAGE - 1) ? 0 : cs + 1;

#pragma unroll
        for (int kk = 0; kk < 4; kk++) {
            const int k0 = kk * 8;
            uint32_t af[4][4];
#pragma unroll
            for (int mf = 0; mf < 4; mf++)
                ldsm_x4(af[mf], aAddr + (mf * 16 * PAD + k0) * 4);
            uint32_t bf[4][2];
#pragma unroll
            for (int np = 0; np < 2; np++) {
                uint32_t bt[4];
                ldsm_x4(bt, bAddr + (np * 16 * PAD + k0) * 4);
                bf[2 * np][0]     = bt[0]; bf[2 * np][1]     = bt[1];
                bf[2 * np + 1][0] = bt[2]; bf[2 * np + 1][1] = bt[3];
            }
#pragma unroll
            for (int mf = 0; mf < 4; mf++)
#pragma unroll
                for (int nf = 0; nf < 4; nf++)
                    mma_tf32(acc[mf][nf], af[mf], bf[nf]);
        }
    }

#pragma unroll
    for (int mf = 0; mf < 4; mf++) {
        const int row = bm + wm * 64 + mf * 16 + gid;
#pragma unroll
        for (int nf = 0; nf < 4; nf++) {
            const int col = bn + wn * 32 + nf * 8 + 2 * tig;
            const float b0 = bias[col], b1 = bias[col + 1];
            float2 v0, v1;
            if (ROUND) {
                v0.x = rnaf(acc[mf][nf][0] + b0); v0.y = rnaf(acc[mf][nf][1] + b1);
                v1.x = rnaf(acc[mf][nf][2] + b0); v1.y = rnaf(acc[mf][nf][3] + b1);
            } else {
                v0.x = acc[mf][nf][0] + b0; v0.y = acc[mf][nf][1] + b1;
                v1.x = acc[mf][nf][2] + b0; v1.y = acc[mf][nf][3] + b1;
            }
            *(float2*)&C[(size_t)row * N + col]       = v0;
            *(float2*)&C[(size_t)(row + 8) * N + col] = v1;
        }
    }
}

// =====================================================================
// QKV GEMM: CTA tile 128x192 (warp tile 64x48), BK=32, 2-stage cp.async,
// ONE sync per chunk, 2 CTAs/SM. Grid 17x16: blockIdx.x<16 => GEMM
// (256 CTAs), blockIdx.x==16 => Wo tf32-convert (16 CTAs, hidden).
// =====================================================================
#define TBN     192
#define AT192_F (128 * PAD)
#define BT192_F (TBN * PAD)
#define STG192_F (AT192_F + BT192_F)
#define G192_SMEM_BYTES (2 * STG192_F * 4)

__global__ __launch_bounds__(256, 2) void gemm_tf32_n192(
    const float* __restrict__ A, const float* __restrict__ B,
    const float* __restrict__ bias, float* __restrict__ C,
    int M, int N, int K,
    const float4* __restrict__ wo, float4* __restrict__ wot)
{
    extern __shared__ float sm[];

    // ---- tail CTA column: Wo conversion (no smem, no barrier use) ----
    if (blockIdx.x == gridDim.x - 1) {
        const int nwork = N4_BIG;                       // 1,048,576 float4
        const int nct   = gridDim.y;                    // 16 CTAs
        const int base  = blockIdx.y * (nwork / nct);
        const int end   = base + (nwork / nct);
        for (int i = base + threadIdx.x; i < end; i += 256) {
            float4 v = wo[i];
            float4 o;
            o.x = rnaf(v.x); o.y = rnaf(v.y); o.z = rnaf(v.z); o.w = rnaf(v.w);
            wot[i] = o;
        }
        return;
    }

    const int tid  = threadIdx.x;
    const int wid  = tid >> 5;
    const int lane = tid & 31;
    const int gid  = lane >> 2;
    const int tig  = lane & 3;
    const int wm   = wid >> 2;
    const int wn   = wid & 3;
    const int bm   = blockIdx.y * 128;
    const int bn   = blockIdx.x * TBN;
    const int nchunk = K >> 5;

    const int arow = lane & 15;
    const int acsh = (lane >> 4) * 4;
    const int brow = ((lane >> 4) << 3) + (lane & 7);
    const int bcsh = ((lane >> 3) & 1) * 4;

    const uint32_t smem_u32 = (uint32_t)__cvta_generic_to_shared(sm);

    auto load_chunk = [&](int s, int j) {
        const uint32_t sA = smem_u32 + (s * STG192_F) * 4;
        const uint32_t sB = sA + AT192_F * 4;
        const float* Ag = A + (size_t)bm * K + j * BK;
        const float* Bg = B + (size_t)bn * K + j * BK;
#pragma unroll
        for (int it = 0; it < 4; it++) {
            const int idx = tid + it * 256;
            const int r = idx >> 3;
            const int c = idx & 7;
            cpasync16(sA + (r * PAD + c * 4) * 4, Ag + (size_t)r * K + c * 4);
        }
#pragma unroll
        for (int it = 0; it < 6; it++) {
            const int idx = tid + it * 256;
            const int r = idx >> 3;
            const int c = idx & 7;
            cpasync16(sB + (r * PAD + c * 4) * 4, Bg + (size_t)r * K + c * 4);
        }
        asm volatile("cp.async.commit_group;" ::: "memory");
    };

    float acc[4][6][4];
#pragma unroll
    for (int mf = 0; mf < 4; mf++)
#pragma unroll
        for (int nf = 0; nf < 6; nf++)
#pragma unroll
            for (int q = 0; q < 4; q++) acc[mf][nf][q] = 0.0f;

    load_chunk(0, 0);

    for (int i = 0; i < nchunk; i++) {
        asm volatile("cp.async.wait_group 0;" ::: "memory");
        __syncthreads();

        if (i + 1 < nchunk) load_chunk((i + 1) & 1, i + 1);

        const uint32_t stA = smem_u32 + ((i & 1) * STG192_F) * 4;
        const uint32_t stB = stA + AT192_F * 4;
        const uint32_t aAddr = stA + ((wm * 64 + arow) * PAD + acsh) * 4;
        const uint32_t bAddr = stB + ((wn * 48 + brow) * PAD + bcsh) * 4;

#pragma unroll
        for (int kk = 0; kk < 4; kk++) {
            const int k0 = kk * 8;
            uint32_t af[4][4];
#pragma unroll
            for (int mf = 0; mf < 4; mf++)
                ldsm_x4(af[mf], aAddr + (mf * 16 * PAD + k0) * 4);
            uint32_t bf[6][2];
#pragma unroll
            for (int np = 0; np < 3; np++) {
                uint32_t bt[4];
                ldsm_x4(bt, bAddr + (np * 16 * PAD + k0) * 4);
                bf[2 * np][0]     = bt[0]; bf[2 * np][1]     = bt[1];
                bf[2 * np + 1][0] = bt[2]; bf[2 * np + 1][1] = bt[3];
            }
#pragma unroll
            for (int mf = 0; mf < 4; mf++)
#pragma unroll
                for (int nf = 0; nf < 6; nf++)
                    mma_tf32(acc[mf][nf], af[mf], bf[nf]);
        }
    }

#pragma unroll
    for (int mf = 0; mf < 4; mf++) {
        const int row = bm + wm * 64 + mf * 16 + gid;
#pragma unroll
        for (int nf = 0; nf < 6; nf++) {
            const int col = bn + wn * 48 + nf * 8 + 2 * tig;
            const float b0 = bias[col], b1 = bias[col + 1];
            float2 v0, v1;
            v0.x = rnaf(acc[mf][nf][0] + b0); v0.y = rnaf(acc[mf][nf][1] + b1);
            v1.x = rnaf(acc[mf][nf][2] + b0); v1.y = rnaf(acc[mf][nf][3] + b1);
            *(float2*)&C[(size_t)row * N + col]       = v0;
            *(float2*)&C[(size_t)(row + 8) * N + col] = v1;
        }
    }
}

// =====================================================================
// Flash attention v6: LPT schedule (makespan 32) + swizzled Vt.
// ldg_V moved after the S-MMA block (shorter register live range).
// =====================================================================
#define QT    128
#define KT    64
#define DPAD  132
#define VPAD  64
#define PPAD  68
#define KOFF  0
#define VOFF  (2 * KT * DPAD)
#define POFF  (VOFF + 2 * QT * VPAD)
#define ATTN_F (POFF + QT * PPAD)
#define ATTN_SMEM_BYTES (ATTN_F * 4)
#define NQB   (SEQ / QT)                      // 16

__global__ __launch_bounds__(256, 1) void attn_tc_kernel(
    const float* __restrict__ QKV, float* __restrict__ Y)
{
    extern __shared__ float sm[];

    const int h    = blockIdx.y;
    const int slot = blockIdx.x;            // 0..8
    const int kvh  = h >> 2;
    const int tid  = threadIdx.x;
    const int wid  = tid >> 5;
    const int lane = tid & 31;
    const int gid  = lane >> 2;
    const int tig  = lane & 3;
    const int w16  = wid * 16;

    int qlist[2];
    int nq;
    if (slot == 0)      { qlist[0] = NQB - 1; nq = 1; }
    else if (slot <= 7) { qlist[0] = NQB - 1 - slot; qlist[1] = slot - 1; nq = 2; }
    else                { qlist[0] = NQB / 2 - 1; nq = 1; }

    const int arow = lane & 15;
    const int acsh = (lane >> 4) * 4;
    const int brow = ((lane >> 4) << 3) + (lane & 7);
    const int bcsh = ((lane >> 3) & 1) * 4;

    const uint32_t smem_u32 = (uint32_t)__cvta_generic_to_shared(sm);

    const float* Qg = QKV + h * DK;
    const float* Kg = QKV + DMODEL + kvh * DK;
    const float* Vg = QKV + DMODEL + KVDIM + kvh * DK;

    const uint32_t kBase = smem_u32 + (KOFF + brow * DPAD + bcsh) * 4;
    const uint32_t vtRegion = smem_u32 + VOFF * 4;
    const uint32_t pAddr = smem_u32 + (POFF + (w16 + arow) * PPAD + acsh) * 4;
    float* Ps = sm + POFF;

    const int b7  = brow & 7;
    const int bq2 = brow >> 2;
    const int bcsh4 = bcsh * 4;

    const int vbr0 = tid >> 5;
    const int vbc0 = tid & 31;
    const float scale = 0.08838834764831845f;

    auto issue_K = [&](int jbi, int buf) {
        const float* src = Kg + (size_t)(jbi * KT) * NQKV;
        const uint32_t dst = smem_u32 + (KOFF + buf * KT * DPAD) * 4;
#pragma unroll
        for (int it = 0; it < 8; it++) {
            const int idx = tid + it * 256;
            const int r = idx >> 5;
            const int c = idx & 31;
            cpasync16(dst + (r * DPAD + c * 4) * 4, src + (size_t)r * NQKV + c * 4);
        }
        asm volatile("cp.async.commit_group;" ::: "memory");
    };
    auto ldg_V = [&](int jbi, float4 vb[2][4]) {
        const float* src = Vg + (size_t)(jbi * KT) * NQKV;
#pragma unroll
        for (int b = 0; b < 2; b++) {
            const int br = vbr0 + b * 8;
#pragma unroll
            for (int j = 0; j < 4; j++)
                vb[b][j] = *(const float4*)&src[(size_t)(br * 4 + j) * NQKV + vbc0 * 4];
        }
    };
    auto sts_Vt = [&](int buf, float4 vb[2][4]) {
        char* vt = (char*)(sm + VOFF + buf * QT * VPAD);
#pragma unroll
        for (int b = 0; b < 2; b++) {
            const int br = vbr0 + b * 8;
            const float* v = (const float*)vb[b];
#pragma unroll
            for (int k = 0; k < 4; k++) {
                float4 w;
                w.x = v[0 * 4 + k]; w.y = v[1 * 4 + k];
                w.z = v[2 * 4 + k]; w.w = v[3 * 4 + k];
                const int row = vbc0 * 4 + k;
                uint32_t off = row * 256 + (br << 4);
                off ^= (uint32_t)(((row & 7) ^ ((row >> 2) & 7)) << 4);
                *(float4*)(vt + off) = w;
            }
        }
    };

    for (int hi = 0; hi < nq; hi++) {
        const int qb = qlist[hi];
        const int q0 = qb * QT;
        const int rg0 = q0 + w16 + gid;
        const int rg1 = rg0 + 8;
        const int njb = 2 * qb + 2;

        asm volatile("cp.async.wait_group 0;" ::: "memory");
        __syncthreads();

        // ---- stage Q (pre-rounded tf32) into K region, ldsm to regs ----
        for (int i = tid; i < QT * 32; i += 256) {
            const int r  = i >> 5;
            const int c4 = (i & 31) << 2;
            *(float4*)&sm[r * DPAD + c4] = *(const float4*)&Qg[(size_t)(q0 + r) * NQKV + c4];
        }
        __syncthreads();
        uint32_t qf[16][4];
        {
            const uint32_t qAddr = smem_u32 + ((w16 + arow) * DPAD + acsh) * 4;
#pragma unroll
            for (int kk = 0; kk < 16; kk++)
                ldsm_x4(qf[kk], qAddr + kk * 32);
        }
        __syncthreads();

        float o_acc[16][4];
#pragma unroll
        for (int nf = 0; nf < 16; nf++)
#pragma unroll
            for (int q = 0; q < 4; q++) o_acc[nf][q] = 0.0f;
        float m0 = -1e30f, m1 = -1e30f, l0 = 0.0f, l1 = 0.0f;

        issue_K(0, 0);
        {
            float4 vb[2][4];
            ldg_V(0, vb);
            sts_Vt(0, vb);
        }

        for (int jb = 0; jb < njb; jb++) {
            const int buf = jb & 1;

            asm volatile("cp.async.wait_group 0;" ::: "memory");
            __syncthreads();

            const bool have_next = (jb + 1 < njb);
            if (have_next) issue_K(jb + 1, buf ^ 1);

            // ---- S = Q @ K^T ----
            float s[8][4];
#pragma unroll
            for (int nf = 0; nf < 8; nf++)
#pragma unroll
                for (int q = 0; q < 4; q++) s[nf][q] = 0.0f;

            const uint32_t kAddr = kBase + (buf * KT * DPAD) * 4;
#pragma unroll
            for (int kk = 0; kk < 16; kk++) {
                const int kd = kk * 8;
                uint32_t bf[8][2];
#pragma unroll
                for (int np = 0; np < 4; np++) {
                    uint32_t bt[4];
                    ldsm_x4(bt, kAddr + (np * 16 * DPAD + kd) * 4);
                    bf[2 * np][0]     = bt[0]; bf[2 * np][1]     = bt[1];
                    bf[2 * np + 1][0] = bt[2]; bf[2 * np + 1][1] = bt[3];
                }
#pragma unroll
                for (int nf = 0; nf < 8; nf++)
                    mma_tf32(s[nf], qf[kk], bf[nf]);
            }

            // V global loads issued here: latency covered by softmax
            float4 vb[2][4];
            if (have_next) ldg_V(jb + 1, vb);

            // ---- scale + mask + online softmax ----
            const int k0 = jb * KT;
            const bool need_mask = (jb >= 2 * qb);
            float mx0 = -1e30f, mx1 = -1e30f;
#pragma unroll
            for (int nf = 0; nf < 8; nf++) {
#pragma unroll
                for (int e = 0; e < 2; e++) {
                    const int jg = k0 + nf * 8 + 2 * tig + e;
                    float v0 = s[nf][e]     * scale;
                    float v1 = s[nf][2 + e] * scale;
                    if (need_mask) {
                        if (jg > rg0) v0 = -1e30f;
                        if (jg > rg1) v1 = -1e30f;
                    }
                    s[nf][e]     = v0;
                    s[nf][2 + e] = v1;
                    mx0 = fmaxf(mx0, v0);
                    mx1 = fmaxf(mx1, v1);
                }
            }
            mx0 = fmaxf(mx0, __shfl_xor_sync(0xffffffffu, mx0, 1));
            mx0 = fmaxf(mx0, __shfl_xor_sync(0xffffffffu, mx0, 2));
            mx1 = fmaxf(mx1, __shfl_xor_sync(0xffffffffu, mx1, 1));
            mx1 = fmaxf(mx1, __shfl_xor_sync(0xffffffffu, mx1, 2));

            const float mn0 = fmaxf(m0, mx0);
            const float mn1 = fmaxf(m1, mx1);
            const float al0 = __expf(m0 - mn0);
            const float al1 = __expf(m1 - mn1);
            m0 = mn0; m1 = mn1;

            float sum0 = 0.0f, sum1 = 0.0f;
#pragma unroll
            for (int nf = 0; nf < 8; nf++) {
                float p00 = __expf(s[nf][0] - mn0);
                float p01 = __expf(s[nf][1] - mn0);
                float p10 = __expf(s[nf][2] - mn1);
                float p11 = __expf(s[nf][3] - mn1);
                sum0 += p00 + p01;
                sum1 += p10 + p11;
                float2 w0; w0.x = rnaf(p00); w0.y = rnaf(p01);
                float2 w1; w1.x = rnaf(p10); w1.y = rnaf(p11);
                const int pc = nf * 8 + 2 * tig;
                *(float2*)&Ps[(w16 + gid)     * PPAD + pc] = w0;
                *(float2*)&Ps[(w16 + gid + 8) * PPAD + pc] = w1;
            }
            sum0 += __shfl_xor_sync(0xffffffffu, sum0, 1);
            sum0 += __shfl_xor_sync(0xffffffffu, sum0, 2);
            sum1 += __shfl_xor_sync(0xffffffffu, sum1, 1);
            sum1 += __shfl_xor_sync(0xffffffffu, sum1, 2);
            l0 = l0 * al0 + sum0;
            l1 = l1 * al1 + sum1;

#pragma unroll
            for (int nf = 0; nf < 16; nf++) {
                o_acc[nf][0] *= al0; o_acc[nf][1] *= al0;
                o_acc[nf][2] *= al1; o_acc[nf][3] *= al1;
            }

            if (have_next) sts_Vt(buf ^ 1, vb);
            __syncwarp();

            // ---- O += P @ V  (P + swizzled Vt via ldmatrix) ----
            const uint32_t vtBuf = vtRegion + buf * (QT * VPAD * 4);
#pragma unroll
            for (int kk = 0; kk < 8; kk++) {
                const int kb4 = kk * 32 + bcsh4;
                uint32_t a[4];
                ldsm_x4(a, pAddr + kk * 32);
                uint32_t bf[16][2];
#pragma unroll
                for (int np = 0; np < 8; np++) {
                    const uint32_t sw = (uint32_t)((b7 ^ ((4 * np + bq2) & 7)) << 4);
                    uint32_t addr = vtBuf + (uint32_t)((np * 16 + brow) * 256) + kb4;
                    addr ^= sw;
                    uint32_t bt[4];
                    ldsm_x4(bt, addr);
                    bf[2 * np][0]     = bt[0]; bf[2 * np][1]     = bt[1];
                    bf[2 * np + 1][0] = bt[2]; bf[2 * np + 1][1] = bt[3];
                }
#pragma unroll
                for (int nf = 0; nf < 16; nf++)
                    mma_tf32(o_acc[nf], a, bf[nf]);
            }
        }

        // ---- epilogue for this job ----
        const float inv0 = 1.0f / l0;
        const float inv1 = 1.0f / l1;
#pragma unroll
        for (int nf = 0; nf < 16; nf++) {
            const int col = h * DK + nf * 8 + 2 * tig;
            float2 v0, v1;
            v0.x = rnaf(o_acc[nf][0] * inv0); v0.y = rnaf(o_acc[nf][1] * inv0);
            v1.x = rnaf(o_acc[nf][2] * inv1); v1.y = rnaf(o_acc[nf][3] * inv1);
            *(float2*)&Y[(size_t)rg0 * DMODEL + col] = v0;
            *(float2*)&Y[(size_t)rg1 * DMODEL + col] = v1;
        }
    }
}

// =====================================================================
// launch
// =====================================================================
extern "C" void kernel_launch(void* const* d_in, const int* in_sizes, int n_in,
                              void* d_out, int out_size)
{
    const float* x  = (const float*)d_in[0];
    const float* Wq = (const float*)d_in[1];
    const float* bq = (const float*)d_in[2];
    const float* Wk = (const float*)d_in[3];
    const float* bk = (const float*)d_in[4];
    const float* Wv = (const float*)d_in[5];
    const float* bv = (const float*)d_in[6];
    const float* Wo = (const float*)d_in[7];
    const float* bo = (const float*)d_in[8];
    float* out = (float*)d_out;

    float *QKVb, *Yb, *xt, *Wqkv, *bqkv, *Wot;
    cudaGetSymbolAddress((void**)&QKVb, g_QKV);
    cudaGetSymbolAddress((void**)&Yb,   g_Y);
    cudaGetSymbolAddress((void**)&xt,   g_xt);
    cudaGetSymbolAddress((void**)&Wqkv, g_Wqkv);
    cudaGetSymbolAddress((void**)&bqkv, g_bqkv);
    cudaGetSymbolAddress((void**)&Wot,  g_Wot);

    cudaFuncSetAttribute(gemm_tf32<false>,
                         cudaFuncAttributeMaxDynamicSharedMemorySize, GEMM_SMEM_BYTES);
    cudaFuncSetAttribute(gemm_tf32_n192,
                         cudaFuncAttributeMaxDynamicSharedMemorySize, G192_SMEM_BYTES);
    cudaFuncSetAttribute(attn_tc_kernel,
                         cudaFuncAttributeMaxDynamicSharedMemorySize, ATTN_SMEM_BYTES);

    dim3 blk(256);

    // round x, Wq, Wk, Wv + fuse bias (Wo handled inside QKV launch)
    cvt_all_kernel<<<512, blk>>>(
        (const float4*)x, (const float4*)Wq, (const float4*)Wk,
        (const float4*)Wv,
        bq, bk, bv,
        (float4*)xt, (float4*)Wqkv, bqkv);

    // fused QKV projection (+ hidden Wo conversion in tail CTA column)
    gemm_tf32_n192<<<dim3(NQKV / TBN + 1, SEQ / 128), blk, G192_SMEM_BYTES>>>(
        xt, Wqkv, bqkv, QKVb, SEQ, NQKV, DMODEL,
        (const float4*)Wo, (float4*)Wot);

    // attention: LPT schedule, 144 CTAs, one wave
    attn_tc_kernel<<<dim3(9, NHEADS), blk, ATTN_SMEM_BYTES>>>(QKVb, Yb);

    gemm_tf32<false><<<dim3(DMODEL / 128, SEQ / 128), blk, GEMM_SMEM_BYTES>>>(
        Yb, Wot, bo, out, SEQ, DMODEL, DMODEL);
}

// round 17
// speedup vs baseline: 1.9477x; 1.7787x over previous
#include <cuda_runtime.h>
#include <cuda_fp16.h>
#include <cstdint>
#include <math.h>

// ---------------- problem constants ----------------
#define SEQ     2048
#define DMODEL  2048
#define KVDIM   512
#define NHEADS  16
#define DK      128
#define NQKV    (DMODEL + 2 * KVDIM)    // 3072

// ---------------- scratch ----------------
__device__ __half g_QKVh [SEQ * NQKV];
__device__ __half g_Yh   [SEQ * DMODEL];
__device__ __half g_xh   [SEQ * DMODEL];
__device__ __half g_Wqkvh[NQKV * DMODEL];
__device__ float  g_bqkv [NQKV];
__device__ __half g_Woh  [DMODEL * DMODEL];

// =====================================================================
// helpers
// =====================================================================
__device__ __forceinline__ float rnaf(float x) {
    uint32_t u;
    asm("cvt.rna.tf32.f32 %0, %1;" : "=r"(u) : "f"(x));
    return __uint_as_float(u);
}
__device__ __forceinline__ uint32_t f22h(float x, float y) {
    __half2 h = __floats2half2_rn(x, y);
    return *(uint32_t*)&h;
}

__device__ __forceinline__ void cpasync16(uint32_t saddr, const void* gaddr) {
    asm volatile("cp.async.cg.shared.global [%0], [%1], 16;" :: "r"(saddr), "l"(gaddr) : "memory");
}

__device__ __forceinline__ void mma_f16(float c[4], const uint32_t a[4], const uint32_t b[2]) {
    asm volatile(
        "mma.sync.aligned.m16n8k16.row.col.f32.f16.f16.f32 "
        "{%0,%1,%2,%3}, {%4,%5,%6,%7}, {%8,%9}, {%0,%1,%2,%3};"
        : "+f"(c[0]), "+f"(c[1]), "+f"(c[2]), "+f"(c[3])
        : "r"(a[0]), "r"(a[1]), "r"(a[2]), "r"(a[3]), "r"(b[0]), "r"(b[1]));
}

__device__ __forceinline__ void ldsm_x4(uint32_t r[4], uint32_t addr) {
    asm volatile("ldmatrix.sync.aligned.m8n8.x4.shared.b16 {%0,%1,%2,%3}, [%4];"
                 : "=r"(r[0]), "=r"(r[1]), "=r"(r[2]), "=r"(r[3]) : "r"(addr));
}
__device__ __forceinline__ void ldsm_x4_t(uint32_t r[4], uint32_t addr) {
    asm volatile("ldmatrix.sync.aligned.m8n8.x4.trans.shared.b16 {%0,%1,%2,%3}, [%4];"
                 : "=r"(r[0]), "=r"(r[1]), "=r"(r[2]), "=r"(r[3]) : "r"(addr));
}

// =====================================================================
// fp16 conversion for x, Wq, Wk, Wv + bias fusion (grid-stride).
// Unit = 8 floats -> uint4 of halfs. Wo handled in QKV GEMM tail.
// =====================================================================
#define N8_BIG (SEQ * DMODEL / 8)
#define N8_KV  (KVDIM * DMODEL / 8)
#define CVTH_TOTAL (2 * N8_BIG + 2 * N8_KV)

__global__ void cvt_h_kernel(
    const float4* __restrict__ x,  const float4* __restrict__ wq,
    const float4* __restrict__ wk, const float4* __restrict__ wv,
    const float*  __restrict__ bq, const float* __restrict__ bk,
    const float*  __restrict__ bv,
    uint4* __restrict__ xh, uint4* __restrict__ wqkvh,
    float* __restrict__ bqkv)
{
    const int total = CVTH_TOTAL + NQKV;
    for (int i = blockIdx.x * blockDim.x + threadIdx.x; i < total;
         i += gridDim.x * blockDim.x) {
        if (i < CVTH_TOTAL) {
            const float4* src;
            uint4* dst;
            int j = i;
            if (j < N8_BIG)                   { src = x;  dst = xh; }
            else if ((j -= N8_BIG) < N8_BIG)  { src = wq; dst = wqkvh; }
            else if ((j -= N8_BIG) < N8_KV)   { src = wk; dst = wqkvh + N8_BIG; }
            else { j -= N8_KV;                  src = wv; dst = wqkvh + N8_BIG + N8_KV; }
            float4 a = src[2 * j];
            float4 b = src[2 * j + 1];
            uint4 o;
            o.x = f22h(a.x, a.y); o.y = f22h(a.z, a.w);
            o.z = f22h(b.x, b.y); o.w = f22h(b.z, b.w);
            dst[j] = o;
        } else {
            int j = i - CVTH_TOTAL;
            float v;
            if (j < DMODEL)              v = bq[j];
            else if (j < DMODEL + KVDIM) v = bk[j - DMODEL];
            else                         v = bv[j - DMODEL - KVDIM];
            bqkv[j] = v;
        }
    }
}

// =====================================================================
// fp16 GEMM common: BK=64 halfs, row pad 72 halfs (144B).
// Fragment index math (16B units identical to tf32 version):
//   A: arow=lane&15, acsh=(lane>>4)*8 halfs
//   B: brow=(lane&7)+((lane>>4)<<3), bcsh=((lane>>3)&1)*8 halfs
// =====================================================================
#define BKH   64
#define PADH  72

// ---------------------------------------------------------------------
// O-projection GEMM: CTA 128x128, warp tile 64x32, 3-stage, 2 CTAs/SM.
// A = Yh (half), B = Woh (half), C = float + bias.
// ---------------------------------------------------------------------
#define TILEH   (128 * PADH)
#define STAGEH  (2 * TILEH)
#define GEMMH_SMEM_BYTES (3 * STAGEH * 2)     // 110,592 B

__global__ __launch_bounds__(256, 2) void gemm_f16_out(
    const __half* __restrict__ A, const __half* __restrict__ B,
    const float* __restrict__ bias, float* __restrict__ C,
    int M, int N, int K)
{
    extern __shared__ char smc[];

    const int tid  = threadIdx.x;
    const int wid  = tid >> 5;
    const int lane = tid & 31;
    const int gid  = lane >> 2;
    const int tig  = lane & 3;
    const int wm   = wid >> 2;
    const int wn   = wid & 3;
    const int bm   = blockIdx.y * 128;
    const int bn   = blockIdx.x * 128;
    const int nchunk = K / BKH;

    const int arow = lane & 15;
    const int acsh = (lane >> 4) * 8;
    const int brow = (lane & 7) + ((lane >> 4) << 3);
    const int bcsh = ((lane >> 3) & 1) * 8;

    const uint32_t smem_u32 = (uint32_t)__cvta_generic_to_shared(smc);

    auto load_chunk = [&](int s, int j) {
        const uint32_t sA = smem_u32 + (s * STAGEH) * 2;
        const uint32_t sB = sA + TILEH * 2;
        const __half* Ag = A + (size_t)bm * K + j * BKH;
        const __half* Bg = B + (size_t)bn * K + j * BKH;
#pragma unroll
        for (int it = 0; it < 4; it++) {
            const int idx = tid + it * 256;     // 0..1023: 128 rows x 8 chunks
            const int r = idx >> 3;
            const int c = idx & 7;
            const uint32_t soff = (r * PADH + c * 8) * 2;
            cpasync16(sA + soff, Ag + (size_t)r * K + c * 8);
            cpasync16(sB + soff, Bg + (size_t)r * K + c * 8);
        }
        asm volatile("cp.async.commit_group;" ::: "memory");
    };

    float acc[4][4][4];
#pragma unroll
    for (int mf = 0; mf < 4; mf++)
#pragma unroll
        for (int nf = 0; nf < 4; nf++)
#pragma unroll
            for (int q = 0; q < 4; q++) acc[mf][nf][q] = 0.0f;

    load_chunk(0, 0);
    load_chunk(1, 1);

    int cs = 0;
    int ls = 2;
    for (int i = 0; i < nchunk; i++) {
        if (i + 1 < nchunk) {
            asm volatile("cp.async.wait_group 1;" ::: "memory");
        } else {
            asm volatile("cp.async.wait_group 0;" ::: "memory");
        }
        __syncthreads();

        const int j = i + 2;
        if (j < nchunk) {
            load_chunk(ls, j);
            ls = (ls == 2) ? 0 : ls + 1;
        }

        const uint32_t stA = smem_u32 + (cs * STAGEH) * 2;
        const uint32_t stB = stA + TILEH * 2;
        const uint32_t aAddr = stA + ((wm * 64 + arow) * PADH + acsh) * 2;
        const uint32_t bAddr = stB + ((wn * 32 + brow) * PADH + bcsh) * 2;
        cs = (cs == 2) ? 0 : cs + 1;

#pragma unroll
        for (int kk = 0; kk < 4; kk++) {
            const int k0 = kk * 16;
            uint32_t af[4][4];
#pragma unroll
            for (int mf = 0; mf < 4; mf++)
                ldsm_x4(af[mf], aAddr + (mf * 16 * PADH + k0) * 2);
            uint32_t bf[4][2];
#pragma unroll
            for (int np = 0; np < 2; np++) {
                uint32_t bt[4];
                ldsm_x4(bt, bAddr + (np * 16 * PADH + k0) * 2);
                bf[2 * np][0]     = bt[0]; bf[2 * np][1]     = bt[1];
                bf[2 * np + 1][0] = bt[2]; bf[2 * np + 1][1] = bt[3];
            }
#pragma unroll
            for (int mf = 0; mf < 4; mf++)
#pragma unroll
                for (int nf = 0; nf < 4; nf++)
                    mma_f16(acc[mf][nf], af[mf], bf[nf]);
        }
    }

#pragma unroll
    for (int mf = 0; mf < 4; mf++) {
        const int row = bm + wm * 64 + mf * 16 + gid;
#pragma unroll
        for (int nf = 0; nf < 4; nf++) {
            const int col = bn + wn * 32 + nf * 8 + 2 * tig;
            const float b0 = bias[col], b1 = bias[col + 1];
            float2 v0, v1;
            v0.x = acc[mf][nf][0] + b0; v0.y = acc[mf][nf][1] + b1;
            v1.x = acc[mf][nf][2] + b0; v1.y = acc[mf][nf][3] + b1;
            *(float2*)&C[(size_t)row * N + col]       = v0;
            *(float2*)&C[(size_t)(row + 8) * N + col] = v1;
        }
    }
}

// ---------------------------------------------------------------------
// QKV GEMM: CTA 128x192 (warp tile 64x48), 2-stage, one sync per chunk,
// 2 CTAs/SM. Grid (17,16): x<16 => GEMM, x==16 => Wo->half (hidden).
// Output half (+bias in fp32).
// ---------------------------------------------------------------------
#define TBNH    192
#define AT_H    (128 * PADH)
#define BT_H    (TBNH * PADH)
#define STG_H   (AT_H + BT_H)
#define G192H_SMEM_BYTES (2 * STG_H * 2)      // 92,160 B

__global__ __launch_bounds__(256, 2) void gemm_f16_qkv(
    const __half* __restrict__ A, const __half* __restrict__ B,
    const float* __restrict__ bias, __half* __restrict__ C,
    int M, int N, int K,
    const float4* __restrict__ wo, uint4* __restrict__ woh)
{
    extern __shared__ char smc[];

    // tail CTA column: Wo -> half (no smem use)
    if (blockIdx.x == gridDim.x - 1) {
        const int nwork = DMODEL * DMODEL / 8;      // 524,288 groups of 8
        const int per   = nwork / gridDim.y;        // 32,768
        const int base  = blockIdx.y * per;
        for (int i = base + threadIdx.x; i < base + per; i += 256) {
            float4 a = wo[2 * i];
            float4 b = wo[2 * i + 1];
            uint4 o;
            o.x = f22h(a.x, a.y); o.y = f22h(a.z, a.w);
            o.z = f22h(b.x, b.y); o.w = f22h(b.z, b.w);
            woh[i] = o;
        }
        return;
    }

    const int tid  = threadIdx.x;
    const int wid  = tid >> 5;
    const int lane = tid & 31;
    const int gid  = lane >> 2;
    const int tig  = lane & 3;
    const int wm   = wid >> 2;
    const int wn   = wid & 3;
    const int bm   = blockIdx.y * 128;
    const int bn   = blockIdx.x * TBNH;
    const int nchunk = K / BKH;

    const int arow = lane & 15;
    const int acsh = (lane >> 4) * 8;
    const int brow = (lane & 7) + ((lane >> 4) << 3);
    const int bcsh = ((lane >> 3) & 1) * 8;

    const uint32_t smem_u32 = (uint32_t)__cvta_generic_to_shared(smc);

    auto load_chunk = [&](int s, int j) {
        const uint32_t sA = smem_u32 + (s * STG_H) * 2;
        const uint32_t sB = sA + AT_H * 2;
        const __half* Ag = A + (size_t)bm * K + j * BKH;
        const __half* Bg = B + (size_t)bn * K + j * BKH;
#pragma unroll
        for (int it = 0; it < 4; it++) {
            const int idx = tid + it * 256;     // A: 128 rows x 8
            const int r = idx >> 3;
            const int c = idx & 7;
            cpasync16(sA + (r * PADH + c * 8) * 2, Ag + (size_t)r * K + c * 8);
        }
#pragma unroll
        for (int it = 0; it < 6; it++) {
            const int idx = tid + it * 256;     // B: 192 rows x 8
            const int r = idx >> 3;
            const int c = idx & 7;
            cpasync16(sB + (r * PADH + c * 8) * 2, Bg + (size_t)r * K + c * 8);
        }
        asm volatile("cp.async.commit_group;" ::: "memory");
    };

    float acc[4][6][4];
#pragma unroll
    for (int mf = 0; mf < 4; mf++)
#pragma unroll
        for (int nf = 0; nf < 6; nf++)
#pragma unroll
            for (int q = 0; q < 4; q++) acc[mf][nf][q] = 0.0f;

    load_chunk(0, 0);

    for (int i = 0; i < nchunk; i++) {
        asm volatile("cp.async.wait_group 0;" ::: "memory");
        __syncthreads();

        if (i + 1 < nchunk) load_chunk((i + 1) & 1, i + 1);

        const uint32_t stA = smem_u32 + ((i & 1) * STG_H) * 2;
        const uint32_t stB = stA + AT_H * 2;
        const uint32_t aAddr = stA + ((wm * 64 + arow) * PADH + acsh) * 2;
        const uint32_t bAddr = stB + ((wn * 48 + brow) * PADH + bcsh) * 2;

#pragma unroll
        for (int kk = 0; kk < 4; kk++) {
            const int k0 = kk * 16;
            uint32_t af[4][4];
#pragma unroll
            for (int mf = 0; mf < 4; mf++)
                ldsm_x4(af[mf], aAddr + (mf * 16 * PADH + k0) * 2);
            uint32_t bf[6][2];
#pragma unroll
            for (int np = 0; np < 3; np++) {
                uint32_t bt[4];
                ldsm_x4(bt, bAddr + (np * 16 * PADH + k0) * 2);
                bf[2 * np][0]     = bt[0]; bf[2 * np][1]     = bt[1];
                bf[2 * np + 1][0] = bt[2]; bf[2 * np + 1][1] = bt[3];
            }
#pragma unroll
            for (int mf = 0; mf < 4; mf++)
#pragma unroll
                for (int nf = 0; nf < 6; nf++)
                    mma_f16(acc[mf][nf], af[mf], bf[nf]);
        }
    }

#pragma unroll
    for (int mf = 0; mf < 4; mf++) {
        const int row = bm + wm * 64 + mf * 16 + gid;
#pragma unroll
        for (int nf = 0; nf < 6; nf++) {
            const int col = bn + wn * 48 + nf * 8 + 2 * tig;
            const float b0 = bias[col], b1 = bias[col + 1];
            uint32_t h0 = f22h(acc[mf][nf][0] + b0, acc[mf][nf][1] + b1);
            uint32_t h1 = f22h(acc[mf][nf][2] + b0, acc[mf][nf][3] + b1);
            *(uint32_t*)&C[(size_t)row * N + col]       = h0;
            *(uint32_t*)&C[(size_t)(row + 8) * N + col] = h1;
        }
    }
}

// =====================================================================
// Flash attention v7 (fp16): LPT schedule, cp.async K AND V (trans
// ldmatrix for V — no register transpose), fp32 softmax/accum.
// smem (halfs): [K dbl 2x64x136 | V dbl 2x64x136 | P 128x72]
// Q staged into the K region before the mainloop.
// =====================================================================
#define QT    128
#define KT    64
#define DPADH 136
#define PPADH 72
#define VOFFH (2 * KT * DPADH)                 // 17408
#define POFFH (2 * VOFFH)                      // 34816
#define ATTNH_F (POFFH + QT * PPADH)           // 44032 halfs
#define ATTNH_SMEM_BYTES (ATTNH_F * 2)         // 88064 B
#define NQB   (SEQ / QT)                       // 16

__global__ __launch_bounds__(256, 1) void attn_f16_kernel(
    const __half* __restrict__ QKV, __half* __restrict__ Y)
{
    extern __shared__ char smc[];
    __half* smh = (__half*)smc;

    const int h    = blockIdx.y;
    const int slot = blockIdx.x;            // 0..8
    const int kvh  = h >> 2;
    const int tid  = threadIdx.x;
    const int wid  = tid >> 5;
    const int lane = tid & 31;
    const int gid  = lane >> 2;
    const int tig  = lane & 3;
    const int w16  = wid * 16;

    int qlist[2];
    int nq;
    if (slot == 0)      { qlist[0] = NQB - 1; nq = 1; }
    else if (slot <= 7) { qlist[0] = NQB - 1 - slot; qlist[1] = slot - 1; nq = 2; }
    else                { qlist[0] = NQB / 2 - 1; nq = 1; }

    const int arow = lane & 15;
    const int acsh = (lane >> 4) * 8;
    const int brow = (lane & 7) + ((lane >> 4) << 3);
    const int bcsh = ((lane >> 3) & 1) * 8;
    // V trans-ldmatrix per-thread source row/col (k-major tiles)
    const int vkr = (lane & 7) + (((lane >> 3) & 1) << 3);
    const int vnc = (lane >> 4) * 8;

    const uint32_t smem_u32 = (uint32_t)__cvta_generic_to_shared(smc);

    const __half* Qg = QKV + h * DK;
    const __half* Kg = QKV + DMODEL + kvh * DK;
    const __half* Vg = QKV + DMODEL + KVDIM + kvh * DK;

    const uint32_t kBase = smem_u32 + (brow * DPADH + bcsh) * 2;
    const uint32_t vBase = smem_u32 + VOFFH * 2 + (vkr * DPADH + vnc) * 2;
    const uint32_t pAddr = smem_u32 + POFFH * 2 + ((w16 + arow) * PPADH + acsh) * 2;
    __half* Ps = smh + POFFH;

    const float scale = 0.08838834764831845f;

    auto issue_KV = [&](int jbi, int buf) {
        const __half* ks = Kg + (size_t)(jbi * KT) * NQKV;
        const __half* vs = Vg + (size_t)(jbi * KT) * NQKV;
        const uint32_t kd = smem_u32 + (buf * KT * DPADH) * 2;
        const uint32_t vd = smem_u32 + (VOFFH + buf * KT * DPADH) * 2;
#pragma unroll
        for (int it = 0; it < 4; it++) {
            const int idx = tid + it * 256;     // 64 rows x 16 chunks
            const int r = idx >> 4;
            const int c = idx & 15;
            const uint32_t so = (r * DPADH + c * 8) * 2;
            cpasync16(kd + so, ks + (size_t)r * NQKV + c * 8);
            cpasync16(vd + so, vs + (size_t)r * NQKV + c * 8);
        }
        asm volatile("cp.async.commit_group;" ::: "memory");
    };

    for (int hi = 0; hi < nq; hi++) {
        const int qb = qlist[hi];
        const int q0 = qb * QT;
        const int rg0 = q0 + w16 + gid;
        const int rg1 = rg0 + 8;
        const int njb = 2 * qb + 2;

        asm volatile("cp.async.wait_group 0;" ::: "memory");
        __syncthreads();

        // ---- stage Q (half) into K region, ldsm to regs ----
        for (int i = tid; i < QT * 16; i += 256) {
            const int r = i >> 4;
            const int c = i & 15;
            *(uint4*)&smh[r * DPADH + c * 8] =
                *(const uint4*)&Qg[(size_t)(q0 + r) * NQKV + c * 8];
        }
        __syncthreads();
        uint32_t qf[8][4];
        {
            const uint32_t qAddr = smem_u32 + ((w16 + arow) * DPADH + acsh) * 2;
#pragma unroll
            for (int kk = 0; kk < 8; kk++)
                ldsm_x4(qf[kk], qAddr + kk * 32);
        }
        __syncthreads();

        float o_acc[16][4];
#pragma unroll
        for (int nf = 0; nf < 16; nf++)
#pragma unroll
            for (int q = 0; q < 4; q++) o_acc[nf][q] = 0.0f;
        float m0 = -1e30f, m1 = -1e30f, l0 = 0.0f, l1 = 0.0f;

        issue_KV(0, 0);

        for (int jb = 0; jb < njb; jb++) {
            const int buf = jb & 1;

            asm volatile("cp.async.wait_group 0;" ::: "memory");
            __syncthreads();

            const bool have_next = (jb + 1 < njb);
            if (have_next) issue_KV(jb + 1, buf ^ 1);

            // ---- S = Q @ K^T  (8 k16 slices) ----
            float s[8][4];
#pragma unroll
            for (int nf = 0; nf < 8; nf++)
#pragma unroll
                for (int q = 0; q < 4; q++) s[nf][q] = 0.0f;

            const uint32_t kAddr = kBase + (buf * KT * DPADH) * 2;
#pragma unroll
            for (int kk = 0; kk < 8; kk++) {
                const int kd = kk * 16;
                uint32_t bf[8][2];
#pragma unroll
                for (int np = 0; np < 4; np++) {
                    uint32_t bt[4];
                    ldsm_x4(bt, kAddr + (np * 16 * DPADH + kd) * 2);
                    bf[2 * np][0]     = bt[0]; bf[2 * np][1]     = bt[1];
                    bf[2 * np + 1][0] = bt[2]; bf[2 * np + 1][1] = bt[3];
                }
#pragma unroll
                for (int nf = 0; nf < 8; nf++)
                    mma_f16(s[nf], qf[kk], bf[nf]);
            }

            // ---- scale + mask + online softmax ----
            const int k0 = jb * KT;
            const bool need_mask = (jb >= 2 * qb);
            float mx0 = -1e30f, mx1 = -1e30f;
#pragma unroll
            for (int nf = 0; nf < 8; nf++) {
#pragma unroll
                for (int e = 0; e < 2; e++) {
                    const int jg = k0 + nf * 8 + 2 * tig + e;
                    float v0 = s[nf][e]     * scale;
                    float v1 = s[nf][2 + e] * scale;
                    if (need_mask) {
                        if (jg > rg0) v0 = -1e30f;
                        if (jg > rg1) v1 = -1e30f;
                    }
                    s[nf][e]     = v0;
                    s[nf][2 + e] = v1;
                    mx0 = fmaxf(mx0, v0);
                    mx1 = fmaxf(mx1, v1);
                }
            }
            mx0 = fmaxf(mx0, __shfl_xor_sync(0xffffffffu, mx0, 1));
            mx0 = fmaxf(mx0, __shfl_xor_sync(0xffffffffu, mx0, 2));
            mx1 = fmaxf(mx1, __shfl_xor_sync(0xffffffffu, mx1, 1));
            mx1 = fmaxf(mx1, __shfl_xor_sync(0xffffffffu, mx1, 2));

            const float mn0 = fmaxf(m0, mx0);
            const float mn1 = fmaxf(m1, mx1);
            const float al0 = __expf(m0 - mn0);
            const float al1 = __expf(m1 - mn1);
            m0 = mn0; m1 = mn1;

            float sum0 = 0.0f, sum1 = 0.0f;
#pragma unroll
            for (int nf = 0; nf < 8; nf++) {
                float p00 = __expf(s[nf][0] - mn0);
                float p01 = __expf(s[nf][1] - mn0);
                float p10 = __expf(s[nf][2] - mn1);
                float p11 = __expf(s[nf][3] - mn1);
                sum0 += p00 + p01;
                sum1 += p10 + p11;
                const int pc = nf * 8 + 2 * tig;
                *(uint32_t*)&Ps[(w16 + gid)     * PPADH + pc] = f22h(p00, p01);
                *(uint32_t*)&Ps[(w16 + gid + 8) * PPADH + pc] = f22h(p10, p11);
            }
            sum0 += __shfl_xor_sync(0xffffffffu, sum0, 1);
            sum0 += __shfl_xor_sync(0xffffffffu, sum0, 2);
            sum1 += __shfl_xor_sync(0xffffffffu, sum1, 1);
            sum1 += __shfl_xor_sync(0xffffffffu, sum1, 2);
            l0 = l0 * al0 + sum0;
            l1 = l1 * al1 + sum1;

#pragma unroll
            for (int nf = 0; nf < 16; nf++) {
                o_acc[nf][0] *= al0; o_acc[nf][1] *= al0;
                o_acc[nf][2] *= al1; o_acc[nf][3] *= al1;
            }
            __syncwarp();

            // ---- O += P @ V  (4 k16 slices; V via trans ldmatrix) ----
            const uint32_t vAddr = vBase + (buf * KT * DPADH) * 2;
#pragma unroll
            for (int kk = 0; kk < 4; kk++) {
                uint32_t a[4];
                ldsm_x4(a, pAddr + kk * 32);
                const uint32_t vSlice = vAddr + (kk * 16 * DPADH) * 2;
#pragma unroll
                for (int np = 0; np < 8; np++) {
                    uint32_t bt[4];
                    ldsm_x4_t(bt, vSlice + (np * 16) * 2);
                    uint32_t b0[2] = { bt[0], bt[1] };
                    uint32_t b1[2] = { bt[2], bt[3] };
                    mma_f16(o_acc[2 * np],     a, b0);
                    mma_f16(o_acc[2 * np + 1], a, b1);
                }
            }
        }

        // ---- epilogue for this job (write Y as half) ----
        const float inv0 = 1.0f / l0;
        const float inv1 = 1.0f / l1;
#pragma unroll
        for (int nf = 0; nf < 16; nf++) {
            const int col = h * DK + nf * 8 + 2 * tig;
            uint32_t h0 = f22h(o_acc[nf][0] * inv0, o_acc[nf][1] * inv0);
            uint32_t h1 = f22h(o_acc[nf][2] * inv1, o_acc[nf][3] * inv1);
            *(uint32_t*)&Y[(size_t)rg0 * DMODEL + col] = h0;
            *(uint32_t*)&Y[(size_t)rg1 * DMODEL + col] = h1;
        }
    }
}

// =====================================================================
// launch
// =====================================================================
extern "C" void kernel_launch(void* const* d_in, const int* in_sizes, int n_in,
                              void* d_out, int out_size)
{
    const float* x  = (const float*)d_in[0];
    const float* Wq = (const float*)d_in[1];
    const float* bq = (const float*)d_in[2];
    const float* Wk = (const float*)d_in[3];
    const float* bk = (const float*)d_in[4];
    const float* Wv = (const float*)d_in[5];
    const float* bv = (const float*)d_in[6];
    const float* Wo = (const float*)d_in[7];
    const float* bo = (const float*)d_in[8];
    float* out = (float*)d_out;

    __half *QKVh, *Yh, *xh, *Wqkvh, *Woh;
    float *bqkv;
    cudaGetSymbolAddress((void**)&QKVh,  g_QKVh);
    cudaGetSymbolAddress((void**)&Yh,    g_Yh);
    cudaGetSymbolAddress((void**)&xh,    g_xh);
    cudaGetSymbolAddress((void**)&Wqkvh, g_Wqkvh);
    cudaGetSymbolAddress((void**)&bqkv,  g_bqkv);
    cudaGetSymbolAddress((void**)&Woh,   g_Woh);

    cudaFuncSetAttribute(gemm_f16_out,
                         cudaFuncAttributeMaxDynamicSharedMemorySize, GEMMH_SMEM_BYTES);
    cudaFuncSetAttribute(gemm_f16_qkv,
                         cudaFuncAttributeMaxDynamicSharedMemorySize, G192H_SMEM_BYTES);
    cudaFuncSetAttribute(attn_f16_kernel,
                         cudaFuncAttributeMaxDynamicSharedMemorySize, ATTNH_SMEM_BYTES);

    dim3 blk(256);

    // convert x, Wq, Wk, Wv to half + fuse bias (Wo in QKV tail)
    cvt_h_kernel<<<512, blk>>>(
        (const float4*)x, (const float4*)Wq, (const float4*)Wk,
        (const float4*)Wv,
        bq, bk, bv,
        (uint4*)xh, (uint4*)Wqkvh, bqkv);

    // fused QKV projection (half out) + hidden Wo conversion
    gemm_f16_qkv<<<dim3(NQKV / TBNH + 1, SEQ / 128), blk, G192H_SMEM_BYTES>>>(
        xh, Wqkvh, bqkv, QKVh, SEQ, NQKV, DMODEL,
        (const float4*)Wo, (uint4*)Woh);

    // attention (fp16 operands, fp32 softmax/accum), LPT schedule
    attn_f16_kernel<<<dim3(9, NHEADS), blk, ATTNH_SMEM_BYTES>>>(QKVh, Yh);

    // output projection (fp32 out + bias)
    gemm_f16_out<<<dim3(DMODEL / 128, SEQ / 128), blk, GEMMH_SMEM_BYTES>>>(
        Yh, Woh, bo, out, SEQ, DMODEL, DMODEL);
}